// round 5
// baseline (speedup 1.0000x reference)
#include <cuda_runtime.h>
#include <cuda_bf16.h>
#include <cstdint>

// Round 5: warp-level tensor cores (mma.sync.m16n8k16 bf16, 3-term split) for
// expert GEMMs; scalar fp32x2 gate/refine; exact-identity tanh via __expf.
// Per warp: 32 tokens. Per CTA: 4 warps = 128 tokens. Persistent grid.

#define NTILES 8192
#define GRID   304

typedef unsigned long long u64;
typedef unsigned int u32;
typedef unsigned short u16;

// ---------------- scalar fp32x2 helpers ----------------
__device__ __forceinline__ u64 pk(float a, float b) {
    u64 r; asm("mov.b64 %0,{%1,%2};" : "=l"(r) : "f"(a), "f"(b)); return r;
}
__device__ __forceinline__ u64 pkdup(float a) { return pk(a, a); }
__device__ __forceinline__ void upk(u64 v, float& a, float& b) {
    asm("mov.b64 {%0,%1},%2;" : "=f"(a), "=f"(b) : "l"(v));
}
__device__ __forceinline__ u64 fma2(u64 a, u64 b, u64 c) {
    u64 d; asm("fma.rn.f32x2 %0,%1,%2,%3;" : "=l"(d) : "l"(a), "l"(b), "l"(c)); return d;
}
__device__ __forceinline__ u64 f2u(float2 v) { return pk(v.x, v.y); }

// ---------------- bf16 pack helpers ----------------
__device__ __forceinline__ u32 fbits(float f) { return __float_as_uint(f); }
// pack truncated-high bf16s of (a,b): low half = hi(a), high half = hi(b)
__device__ __forceinline__ u32 prmt_hi(u32 a, u32 b) {
    u32 d; asm("prmt.b32 %0,%1,%2,0x7632;" : "=r"(d) : "r"(a), "r"(b)); return d;
}
// pack rn-bf16 of (lo_val -> low half, hi_val -> high half)
__device__ __forceinline__ u32 cvt_bf2(float lov, float hiv) {
    u32 d; asm("cvt.rn.bf16x2.f32 %0,%1,%2;" : "=r"(d) : "f"(hiv), "f"(lov)); return d;
}
__device__ __forceinline__ float truncf16(float v) {
    return __uint_as_float(fbits(v) & 0xFFFF0000u);
}

__device__ __forceinline__ float tanh_acc(float v) {
    float e = __expf(2.0f * v);
    return 1.0f - __fdividef(2.0f, e + 1.0f);
}

// ---------------- mma.sync m16n8k16 bf16, f32 accum ----------------
__device__ __forceinline__ void mma16816(float& d0, float& d1, float& d2, float& d3,
                                         u32 a0, u32 a1, u32 a2, u32 a3,
                                         u32 b0, u32 b1) {
    asm volatile("mma.sync.aligned.m16n8k16.row.col.f32.bf16.bf16.f32 "
                 "{%0,%1,%2,%3},{%4,%5,%6,%7},{%8,%9},{%0,%1,%2,%3};"
                 : "+f"(d0), "+f"(d1), "+f"(d2), "+f"(d3)
                 : "r"(a0), "r"(a1), "r"(a2), "r"(a3), "r"(b0), "r"(b1));
}

// ---------------- SMEM layout (bytes) ----------------
// B1 (W1 as B-frag layout [n=256][k=16] bf16, row stride 36B): hi, lo
#define B1H   0
#define B1L   9216
// B2 (W2 [e][n=32][k=32] bf16, row stride 72B): hi, lo
#define B2H   18432
#define B2L   36864
// fp32 weights
#define FP_B  55296
#define FG1   0
#define FGB1  640
#define FG2   704
#define FGB2  1216
#define FB1f  1224
#define FB2f  1480
#define FW3   1736
#define FB3   2248
#define FR1   2264
#define FRB1  3032
#define FR2   3096
#define FRB2  3224
// per-warp activation region
#define ACT_B 68208
#define WSZ   7936
#define OXH   0       // x hi  [32 rows][16 k] bf16, stride 32B
#define OXL   1024
#define OH1H  2048    // h1 hi [32 rows][32 k] bf16, stride 72B
#define OH1L  4352
#define OWB   6656    // wexp [32 tok][8] f32
#define OFB   7680    // fused [32 tok] float2
#define SMEM_TOTAL (ACT_B + 4 * WSZ)   // 99952

extern __shared__ char smem_raw[];

__global__ void __launch_bounds__(128, 2)
moe_mma_kernel(const float* __restrict__ X,
               const float* __restrict__ W1, const float* __restrict__ b1,
               const float* __restrict__ W2, const float* __restrict__ b2,
               const float* __restrict__ W3, const float* __restrict__ b3,
               const float* __restrict__ G1, const float* __restrict__ gb1,
               const float* __restrict__ G2, const float* __restrict__ gb2,
               const float* __restrict__ R1, const float* __restrict__ rb1,
               const float* __restrict__ R2, const float* __restrict__ rb2,
               float* __restrict__ out)
{
    const int tid  = threadIdx.x;
    const int wid  = tid >> 5;
    const int lane = tid & 31;
    const int grp  = lane >> 2;   // 0..7
    const int tig  = lane & 3;    // 0..3
    float* sf = reinterpret_cast<float*>(smem_raw + FP_B);

    // ---------- one-time weight prep ----------
    for (int i = tid; i < 55296 / 4; i += 128)
        reinterpret_cast<u32*>(smem_raw)[i] = 0;
    __syncthreads();
    // W1[e][k][j] -> B1 [n=e*32+j][k], hi = trunc, lo = rn(w - hi)
    for (int idx = tid; idx < 2560; idx += 128) {
        int e = idx / 320, r = idx % 320, k = r >> 5, j = r & 31;
        float w = W1[idx];
        u32 bits = fbits(w);
        float hi_f = __uint_as_float(bits & 0xFFFF0000u);
        __nv_bfloat16 lo = __float2bfloat16(w - hi_f);
        int n = e * 32 + j;
        *reinterpret_cast<u16*>(smem_raw + B1H + n * 36 + k * 2) = (u16)(bits >> 16);
        *reinterpret_cast<u16*>(smem_raw + B1L + n * 36 + k * 2) = *reinterpret_cast<u16*>(&lo);
    }
    // W2[e][k][n] -> B2 [(e*32+n)][k]
    for (int idx = tid; idx < 8192; idx += 128) {
        int e = idx >> 10, r = idx & 1023, k = r >> 5, n = r & 31;
        float w = W2[idx];
        u32 bits = fbits(w);
        float hi_f = __uint_as_float(bits & 0xFFFF0000u);
        __nv_bfloat16 lo = __float2bfloat16(w - hi_f);
        int ro = (e * 32 + n) * 72 + k * 2;
        *reinterpret_cast<u16*>(smem_raw + B2H + ro) = (u16)(bits >> 16);
        *reinterpret_cast<u16*>(smem_raw + B2L + ro) = *reinterpret_cast<u16*>(&lo);
    }
    // fp32 copies
    for (int i = tid; i < 640; i += 128) sf[FG1 + i]  = G1[i];
    for (int i = tid; i < 64;  i += 128) sf[FGB1 + i] = gb1[i];
    for (int i = tid; i < 512; i += 128) sf[FG2 + i]  = G2[i];
    for (int i = tid; i < 8;   i += 128) sf[FGB2 + i] = gb2[i];
    for (int i = tid; i < 256; i += 128) sf[FB1f + i] = b1[i];
    for (int i = tid; i < 256; i += 128) sf[FB2f + i] = b2[i];
    for (int i = tid; i < 512; i += 128) sf[FW3 + i]  = W3[i];
    for (int i = tid; i < 16;  i += 128) sf[FB3 + i]  = b3[i];
    for (int i = tid; i < 768; i += 128) sf[FR1 + i]  = R1[i];
    for (int i = tid; i < 64;  i += 128) sf[FRB1 + i] = rb1[i];
    for (int i = tid; i < 128; i += 128) sf[FR2 + i]  = R2[i];
    if (tid < 2) sf[FRB2 + tid] = rb2[tid];
    __syncthreads();

    char* wbase = smem_raw + ACT_B + wid * WSZ;
    char* xh  = wbase + OXH;
    char* xl  = wbase + OXL;
    char* h1h = wbase + OH1H;
    char* h1l = wbase + OH1L;
    char* wb  = wbase + OWB;
    char* fb  = wbase + OFB;

    // thread's assigned output row for L3/fused accumulation
    const int row_f = grp + ((tig >> 1) << 4) + ((tig & 1) << 3);

    for (int tile = blockIdx.x; tile < NTILES; tile += gridDim.x) {
        const int tok = tile * 128 + wid * 32 + lane;

        // ---- load own token's x ----
        float x[10];
        {
            const float2* xp = reinterpret_cast<const float2*>(X + (size_t)tok * 10);
            #pragma unroll
            for (int i = 0; i < 5; i++) { float2 v = xp[i]; x[2*i] = v.x; x[2*i+1] = v.y; }
        }

        // ---- gate (scalar, own token): 10->64 relu fused with 64->8, softmax ----
        float wsum;
        {
            u64 l2a[4];
            const float2* gb2p = (const float2*)(sf + FGB2);
            #pragma unroll
            for (int j = 0; j < 4; j++) l2a[j] = f2u(gb2p[j]);
            #pragma unroll 1
            for (int c = 0; c < 4; c++) {
                u64 acc[8];
                const float2* bp = (const float2*)(sf + FGB1 + c * 16);
                #pragma unroll
                for (int j = 0; j < 8; j++) acc[j] = f2u(bp[j]);
                #pragma unroll
                for (int k = 0; k < 10; k++) {
                    u64 m = pkdup(x[k]);
                    const float4* wr = (const float4*)(sf + FG1 + k * 64 + c * 16);
                    #pragma unroll
                    for (int j = 0; j < 4; j++) {
                        float4 w = wr[j];
                        acc[2*j]   = fma2(m, pk(w.x, w.y), acc[2*j]);
                        acc[2*j+1] = fma2(m, pk(w.z, w.w), acc[2*j+1]);
                    }
                }
                #pragma unroll
                for (int j = 0; j < 8; j++) {
                    const float4* g2r = (const float4*)(sf + FG2 + (c * 16 + 2 * j) * 8);
                    float4 ra0 = g2r[0], ra1 = g2r[1], rb0 = g2r[2], rb1_ = g2r[3];
                    float p, q; upk(acc[j], p, q);
                    p = fmaxf(p, 0.f); q = fmaxf(q, 0.f);
                    u64 mp = pkdup(p), mq = pkdup(q);
                    l2a[0] = fma2(mp, pk(ra0.x, ra0.y), l2a[0]);
                    l2a[1] = fma2(mp, pk(ra0.z, ra0.w), l2a[1]);
                    l2a[2] = fma2(mp, pk(ra1.x, ra1.y), l2a[2]);
                    l2a[3] = fma2(mp, pk(ra1.z, ra1.w), l2a[3]);
                    l2a[0] = fma2(mq, pk(rb0.x, rb0.y), l2a[0]);
                    l2a[1] = fma2(mq, pk(rb0.z, rb0.w), l2a[1]);
                    l2a[2] = fma2(mq, pk(rb1_.x, rb1_.y), l2a[2]);
                    l2a[3] = fma2(mq, pk(rb1_.z, rb1_.w), l2a[3]);
                }
            }
            float l[8];
            #pragma unroll
            for (int j = 0; j < 4; j++) upk(l2a[j], l[2*j], l[2*j+1]);
            float m = l[0];
            #pragma unroll
            for (int i = 1; i < 8; i++) m = fmaxf(m, l[i]);
            wsum = 0.f;
            float we[8];
            #pragma unroll
            for (int i = 0; i < 8; i++) { we[i] = __expf(l[i] - m); wsum += we[i]; }
            // store unnormalized gate weights for cross-lane reads
            #pragma unroll
            for (int i = 0; i < 8; i += 2)
                *reinterpret_cast<float2*>(wb + lane * 32 + i * 4) = make_float2(we[i], we[i+1]);
        }

        // ---- stage x split (row = lane, [16 k] bf16 hi/lo, zero-padded) ----
        {
            u32 xsh[8], xsl[8];
            #pragma unroll
            for (int i = 0; i < 5; i++) {
                u32 b0 = fbits(x[2*i]), b1b = fbits(x[2*i+1]);
                xsh[i] = prmt_hi(b0, b1b);
                xsl[i] = cvt_bf2(x[2*i] - truncf16(x[2*i]), x[2*i+1] - truncf16(x[2*i+1]));
            }
            xsh[5] = xsh[6] = xsh[7] = 0u; xsl[5] = xsl[6] = xsl[7] = 0u;
            uint4* ph = reinterpret_cast<uint4*>(xh + lane * 32);
            ph[0] = make_uint4(xsh[0], xsh[1], xsh[2], xsh[3]);
            ph[1] = make_uint4(xsh[4], xsh[5], xsh[6], xsh[7]);
            uint4* pl = reinterpret_cast<uint4*>(xl + lane * 32);
            pl[0] = make_uint4(xsl[0], xsl[1], xsl[2], xsl[3]);
            pl[1] = make_uint4(xsl[4], xsl[5], xsl[6], xsl[7]);
        }
        __syncwarp();

        // ---- load x A-fragments (held across all experts) ----
        u32 axh[2][4], axl[2][4];
        #pragma unroll
        for (int mt = 0; mt < 2; mt++) {
            const char* bh = xh + (mt * 16 + grp) * 32 + tig * 4;
            axh[mt][0] = *(const u32*)(bh);
            axh[mt][1] = *(const u32*)(bh + 8 * 32);
            axh[mt][2] = *(const u32*)(bh + 16);
            axh[mt][3] = *(const u32*)(bh + 8 * 32 + 16);
            const char* bl = xl + (mt * 16 + grp) * 32 + tig * 4;
            axl[mt][0] = *(const u32*)(bl);
            axl[mt][1] = *(const u32*)(bl + 8 * 32);
            axl[mt][2] = *(const u32*)(bl + 16);
            axl[mt][3] = *(const u32*)(bl + 8 * 32 + 16);
        }

        float fused0 = 0.f, fused1 = 0.f;

        #pragma unroll 1
        for (int e = 0; e < 8; e++) {
            // ======== L1: x[16] @ W1[16x32] -> h1, split & stage ========
            const char* b1hp = smem_raw + B1H + (e * 32 + grp) * 36 + tig * 4;
            const char* b1lp = smem_raw + B1L + (e * 32 + grp) * 36 + tig * 4;
            #pragma unroll
            for (int nt = 0; nt < 4; nt++) {
                u32 bh0 = *(const u32*)(b1hp + nt * 288);
                u32 bh1 = *(const u32*)(b1hp + nt * 288 + 16);
                u32 bl0 = *(const u32*)(b1lp + nt * 288);
                u32 bl1 = *(const u32*)(b1lp + nt * 288 + 16);
                float2 bias = *(const float2*)(sf + FB1f + e * 32 + nt * 8 + 2 * tig);
                #pragma unroll
                for (int mt = 0; mt < 2; mt++) {
                    float d0 = 0.f, d1 = 0.f, d2 = 0.f, d3 = 0.f;
                    mma16816(d0, d1, d2, d3, axh[mt][0], axh[mt][1], axh[mt][2], axh[mt][3], bh0, bh1);
                    mma16816(d0, d1, d2, d3, axh[mt][0], axh[mt][1], axh[mt][2], axh[mt][3], bl0, bl1);
                    mma16816(d0, d1, d2, d3, axl[mt][0], axl[mt][1], axl[mt][2], axl[mt][3], bh0, bh1);
                    float v0 = fmaxf(d0 + bias.x, 0.f);
                    float v1 = fmaxf(d1 + bias.y, 0.f);
                    float v2 = fmaxf(d2 + bias.x, 0.f);
                    float v3 = fmaxf(d3 + bias.y, 0.f);
                    int r0 = mt * 16 + grp;
                    int co = (nt * 8 + 2 * tig) * 2;
                    char* ph = h1h + r0 * 72 + co;
                    *(u32*)ph            = prmt_hi(fbits(v0), fbits(v1));
                    *(u32*)(ph + 8 * 72) = prmt_hi(fbits(v2), fbits(v3));
                    char* pl = h1l + r0 * 72 + co;
                    *(u32*)pl            = cvt_bf2(v0 - truncf16(v0), v1 - truncf16(v1));
                    *(u32*)(pl + 8 * 72) = cvt_bf2(v2 - truncf16(v2), v3 - truncf16(v3));
                }
            }
            __syncwarp();

            // ======== L2: h1[32] @ W2[32x32], fused L3 (32->2) ========
            u32 ah[2][2][4], al[2][2][4];
            #pragma unroll
            for (int mt = 0; mt < 2; mt++) {
                #pragma unroll
                for (int kt = 0; kt < 2; kt++) {
                    const char* bh = h1h + (mt * 16 + grp) * 72 + kt * 32 + tig * 4;
                    ah[mt][kt][0] = *(const u32*)(bh);
                    ah[mt][kt][1] = *(const u32*)(bh + 8 * 72);
                    ah[mt][kt][2] = *(const u32*)(bh + 16);
                    ah[mt][kt][3] = *(const u32*)(bh + 8 * 72 + 16);
                    const char* bl = h1l + (mt * 16 + grp) * 72 + kt * 32 + tig * 4;
                    al[mt][kt][0] = *(const u32*)(bl);
                    al[mt][kt][1] = *(const u32*)(bl + 8 * 72);
                    al[mt][kt][2] = *(const u32*)(bl + 16);
                    al[mt][kt][3] = *(const u32*)(bl + 8 * 72 + 16);
                }
            }
            float o0[4] = {0.f, 0.f, 0.f, 0.f};
            float o1[4] = {0.f, 0.f, 0.f, 0.f};
            #pragma unroll
            for (int nt = 0; nt < 4; nt++) {
                const char* b2hp = smem_raw + B2H + (e * 32 + nt * 8 + grp) * 72 + tig * 4;
                const char* b2lp = smem_raw + B2L + (e * 32 + nt * 8 + grp) * 72 + tig * 4;
                u32 bh[2][2], bl[2][2];
                #pragma unroll
                for (int kt = 0; kt < 2; kt++) {
                    bh[kt][0] = *(const u32*)(b2hp + kt * 32);
                    bh[kt][1] = *(const u32*)(b2hp + kt * 32 + 16);
                    bl[kt][0] = *(const u32*)(b2lp + kt * 32);
                    bl[kt][1] = *(const u32*)(b2lp + kt * 32 + 16);
                }
                float2 bias = *(const float2*)(sf + FB2f + e * 32 + nt * 8 + 2 * tig);
                float2 w3a  = *(const float2*)(sf + FW3 + (e * 32 + nt * 8 + 2 * tig) * 2);
                float2 w3b  = *(const float2*)(sf + FW3 + (e * 32 + nt * 8 + 2 * tig) * 2 + 2);
                #pragma unroll
                for (int mt = 0; mt < 2; mt++) {
                    float d0 = 0.f, d1 = 0.f, d2 = 0.f, d3 = 0.f;
                    mma16816(d0, d1, d2, d3, ah[mt][0][0], ah[mt][0][1], ah[mt][0][2], ah[mt][0][3], bh[0][0], bh[0][1]);
                    mma16816(d0, d1, d2, d3, ah[mt][0][0], ah[mt][0][1], ah[mt][0][2], ah[mt][0][3], bl[0][0], bl[0][1]);
                    mma16816(d0, d1, d2, d3, al[mt][0][0], al[mt][0][1], al[mt][0][2], al[mt][0][3], bh[0][0], bh[0][1]);
                    mma16816(d0, d1, d2, d3, ah[mt][1][0], ah[mt][1][1], ah[mt][1][2], ah[mt][1][3], bh[1][0], bh[1][1]);
                    mma16816(d0, d1, d2, d3, ah[mt][1][0], ah[mt][1][1], ah[mt][1][2], ah[mt][1][3], bl[1][0], bl[1][1]);
                    mma16816(d0, d1, d2, d3, al[mt][1][0], al[mt][1][1], al[mt][1][2], al[mt][1][3], bh[1][0], bh[1][1]);
                    float v0 = fmaxf(d0 + bias.x, 0.f);
                    float v1 = fmaxf(d1 + bias.y, 0.f);
                    float v2 = fmaxf(d2 + bias.x, 0.f);
                    float v3 = fmaxf(d3 + bias.y, 0.f);
                    o0[mt*2+0] += v0 * w3a.x + v1 * w3b.x;
                    o1[mt*2+0] += v0 * w3a.y + v1 * w3b.y;
                    o0[mt*2+1] += v2 * w3a.x + v3 * w3b.x;
                    o1[mt*2+1] += v2 * w3a.y + v3 * w3b.y;
                }
            }
            // butterfly reduce over quad (tig)
            #pragma unroll
            for (int i = 0; i < 4; i++) {
                o0[i] += __shfl_xor_sync(0xFFFFFFFFu, o0[i], 1);
                o0[i] += __shfl_xor_sync(0xFFFFFFFFu, o0[i], 2);
                o1[i] += __shfl_xor_sync(0xFFFFFFFFu, o1[i], 1);
                o1[i] += __shfl_xor_sync(0xFFFFFFFFu, o1[i], 2);
            }
            // thread handles row_f = row index (tig selects which of its 4 rows)
            float s0 = o0[tig], s1 = o1[tig];
            float2 b3e = *(const float2*)(sf + FB3 + e * 2);
            s0 = tanh_acc(s0 + b3e.x);
            s1 = tanh_acc(s1 + b3e.y);
            float wne = *reinterpret_cast<const float*>(wb + row_f * 32 + e * 4);
            fused0 += wne * s0;
            fused1 += wne * s1;
            __syncwarp();
        }

        // ---- exchange fused back to own-token lanes ----
        *reinterpret_cast<float2*>(fb + row_f * 8) = make_float2(fused0, fused1);
        __syncwarp();
        float2 fu = *reinterpret_cast<const float2*>(fb + lane * 8);
        __syncwarp();

        // ---- refine (scalar, own token): concat(12) -> 64 relu -> 2 tanh ----
        float rin[12];
        {
            float inv = 1.0f / wsum;
            rin[0] = fu.x * inv; rin[1] = fu.y * inv;
            #pragma unroll
            for (int i = 0; i < 10; i++) rin[2 + i] = x[i];
        }
        u64 racc = f2u(*reinterpret_cast<const float2*>(sf + FRB2));
        #pragma unroll 1
        for (int c = 0; c < 4; c++) {
            u64 acc[8];
            const float2* bp = (const float2*)(sf + FRB1 + c * 16);
            #pragma unroll
            for (int j = 0; j < 8; j++) acc[j] = f2u(bp[j]);
            #pragma unroll
            for (int k = 0; k < 12; k++) {
                u64 m = pkdup(rin[k]);
                const float4* wr = (const float4*)(sf + FR1 + k * 64 + c * 16);
                #pragma unroll
                for (int j = 0; j < 4; j++) {
                    float4 w = wr[j];
                    acc[2*j]   = fma2(m, pk(w.x, w.y), acc[2*j]);
                    acc[2*j+1] = fma2(m, pk(w.z, w.w), acc[2*j+1]);
                }
            }
            #pragma unroll
            for (int j = 0; j < 8; j++) {
                const float2* r2 = (const float2*)(sf + FR2 + (c * 16 + 2 * j) * 2);
                u64 we = f2u(r2[0]), wo = f2u(r2[1]);
                float p, q; upk(acc[j], p, q);
                p = fmaxf(p, 0.f); q = fmaxf(q, 0.f);
                racc = fma2(pkdup(p), we, racc);
                racc = fma2(pkdup(q), wo, racc);
            }
        }
        {
            float y0, y1; upk(racc, y0, y1);
            reinterpret_cast<float2*>(out)[tok] =
                make_float2(tanh_acc(y0), tanh_acc(y1));
        }
    }
}

extern "C" void kernel_launch(void* const* d_in, const int* in_sizes, int n_in,
                              void* d_out, int out_size)
{
    (void)in_sizes; (void)n_in; (void)out_size;
    const float* X   = (const float*)d_in[0];
    const float* W1  = (const float*)d_in[1];
    const float* b1  = (const float*)d_in[2];
    const float* W2  = (const float*)d_in[3];
    const float* b2  = (const float*)d_in[4];
    const float* W3  = (const float*)d_in[5];
    const float* b3  = (const float*)d_in[6];
    const float* G1  = (const float*)d_in[7];
    const float* gb1 = (const float*)d_in[8];
    const float* G2  = (const float*)d_in[9];
    const float* gb2 = (const float*)d_in[10];
    const float* R1  = (const float*)d_in[11];
    const float* rb1 = (const float*)d_in[12];
    const float* R2  = (const float*)d_in[13];
    const float* rb2 = (const float*)d_in[14];

    cudaFuncSetAttribute(moe_mma_kernel,
                         cudaFuncAttributeMaxDynamicSharedMemorySize, SMEM_TOTAL);

    moe_mma_kernel<<<GRID, 128, SMEM_TOTAL>>>(
        X, W1, b1, W2, b2, W3, b3, G1, gb1, G2, gb2, R1, rb1, R2, rb2,
        (float*)d_out);
}

// round 6
// speedup vs baseline: 1.6216x; 1.6216x over previous
#include <cuda_runtime.h>
#include <cuda_bf16.h>
#include <cstdint>

// Round 6: expert-specialized warps; all expert weights as register-resident
// mma.sync B-fragments; L1 D-frag reused in-register as L2 A-frag (no h1 SMEM).
// CTA = 256 threads = 8 warps (warp e = expert e), tile = 256 tokens.

#define NTILES 4096
#define GRID   592

typedef unsigned long long u64;
typedef unsigned int u32;

// ---------------- scalar fp32x2 helpers ----------------
__device__ __forceinline__ u64 pk(float a, float b) {
    u64 r; asm("mov.b64 %0,{%1,%2};" : "=l"(r) : "f"(a), "f"(b)); return r;
}
__device__ __forceinline__ u64 pkdup(float a) { return pk(a, a); }
__device__ __forceinline__ void upk(u64 v, float& a, float& b) {
    asm("mov.b64 {%0,%1},%2;" : "=f"(a), "=f"(b) : "l"(v));
}
__device__ __forceinline__ u64 fma2(u64 a, u64 b, u64 c) {
    u64 d; asm("fma.rn.f32x2 %0,%1,%2,%3;" : "=l"(d) : "l"(a), "l"(b), "l"(c)); return d;
}
__device__ __forceinline__ u64 f2u(float2 v) { return pk(v.x, v.y); }

// ---------------- bf16 helpers ----------------
__device__ __forceinline__ u32 fbits(float f) { return __float_as_uint(f); }
__device__ __forceinline__ u32 prmt_hi(u32 a, u32 b) {           // lo=hi(a), hi=hi(b)
    u32 d; asm("prmt.b32 %0,%1,%2,0x7632;" : "=r"(d) : "r"(a), "r"(b)); return d;
}
__device__ __forceinline__ u32 cvt_bf2(float lov, float hiv) {   // lo=rn(lov), hi=rn(hiv)
    u32 d; asm("cvt.rn.bf16x2.f32 %0,%1,%2;" : "=r"(d) : "f"(hiv), "f"(lov)); return d;
}
__device__ __forceinline__ float truncf16(float v) {
    return __uint_as_float(fbits(v) & 0xFFFF0000u);
}
__device__ __forceinline__ float tanh_acc(float v) {
    float e = __expf(2.0f * v);
    return 1.0f - __fdividef(2.0f, e + 1.0f);
}

// ---------------- mma / ldmatrix ----------------
__device__ __forceinline__ void mma16816(float& d0, float& d1, float& d2, float& d3,
                                         u32 a0, u32 a1, u32 a2, u32 a3,
                                         u32 b0, u32 b1) {
    asm volatile("mma.sync.aligned.m16n8k16.row.col.f32.bf16.bf16.f32 "
                 "{%0,%1,%2,%3},{%4,%5,%6,%7},{%8,%9},{%0,%1,%2,%3};"
                 : "+f"(d0), "+f"(d1), "+f"(d2), "+f"(d3)
                 : "r"(a0), "r"(a1), "r"(a2), "r"(a3), "r"(b0), "r"(b1));
}
__device__ __forceinline__ void ldm_x4(u32* r, u32 addr) {
    asm volatile("ldmatrix.sync.aligned.m8n8.x4.shared.b16 {%0,%1,%2,%3}, [%4];"
                 : "=r"(r[0]), "=r"(r[1]), "=r"(r[2]), "=r"(r[3]) : "r"(addr));
}
__device__ __forceinline__ u32 smem_to_u32(const void* p) {
    u32 a;
    asm("{ .reg .u64 t; cvta.to.shared.u64 t, %1; cvt.u32.u64 %0, t; }" : "=r"(a) : "l"(p));
    return a;
}

// split a weight into (hi-pair, lo-pair) packed bf16x2 from two floats
__device__ __forceinline__ void split_pair(float a, float b, u32& hi, u32& lo) {
    hi = prmt_hi(fbits(a), fbits(b));
    lo = cvt_bf2(a - truncf16(a), b - truncf16(b));
}

// ---------------- SMEM layout (bytes) ----------------
#define XB 0            // x fragments: 256 rows x 80B (32B hi, 32B lo, 16B pad)
#define WX 20480        // wexp [8 experts][256 tok] f32
#define FU 28672        // fused partials [8][256] float2
#define SF 45056        // fp32 gate/refine weights
// sf offsets (floats)
#define FG1  0
#define FGB1 640
#define FG2  704
#define FGB2 1216
#define FR1  1224
#define FRB1 1992
#define FR2  2056
#define FRB2 2184
#define SF_FLOATS 2186
#define SMEM_TOTAL (SF + SF_FLOATS * 4 + 8)

extern __shared__ char smem_raw[];

__global__ void __launch_bounds__(256, 1)
moe_r6_kernel(const float* __restrict__ X,
              const float* __restrict__ W1, const float* __restrict__ b1,
              const float* __restrict__ W2, const float* __restrict__ b2,
              const float* __restrict__ W3, const float* __restrict__ b3,
              const float* __restrict__ G1, const float* __restrict__ gb1,
              const float* __restrict__ G2, const float* __restrict__ gb2,
              const float* __restrict__ R1, const float* __restrict__ rb1,
              const float* __restrict__ R2, const float* __restrict__ rb2,
              float* __restrict__ out)
{
    const int tid  = threadIdx.x;
    const int wid  = tid >> 5;     // = expert id
    const int lane = tid & 31;
    const int grp  = lane >> 2;
    const int tig  = lane & 3;
    float* sf = reinterpret_cast<float*>(smem_raw + SF);
    const u32 sbase = smem_to_u32(smem_raw);

    // ---- stage gate/refine fp32 weights into SMEM ----
    for (int i = tid; i < 640; i += 256) sf[FG1 + i]  = G1[i];
    for (int i = tid; i < 64;  i += 256) sf[FGB1 + i] = gb1[i];
    for (int i = tid; i < 512; i += 256) sf[FG2 + i]  = G2[i];
    for (int i = tid; i < 8;   i += 256) sf[FGB2 + i] = gb2[i];
    for (int i = tid; i < 768; i += 256) sf[FR1 + i]  = R1[i];
    for (int i = tid; i < 64;  i += 256) sf[FRB1 + i] = rb1[i];
    for (int i = tid; i < 128; i += 256) sf[FR2 + i]  = R2[i];
    if (tid < 2) sf[FRB2 + tid] = rb2[tid];

    // ---- load this warp's expert weights into register fragments (one time) ----
    const int e = wid;
    u32 b1h[4][2], b1l[4][2];           // [nt][b0/b1]
    u32 b2h[4][2][2], b2l[4][2][2];     // [nt][kt][b0/b1]
    float bias1[4][2], bias2[4][2], w3r[4][2][2];
    #pragma unroll
    for (int nt = 0; nt < 4; nt++) {
        int n = nt * 8 + grp;
        // L1 b0: k = 2tig, 2tig+1 (< 8, always valid)
        {
            float wa = W1[e * 320 + (2 * tig)     * 32 + n];
            float wb = W1[e * 320 + (2 * tig + 1) * 32 + n];
            split_pair(wa, wb, b1h[nt][0], b1l[nt][0]);
        }
        // L1 b1: k = 2tig+8, 2tig+9 (valid only when < 10 -> tig==0)
        {
            float wa = (2 * tig + 8 < 10) ? W1[e * 320 + (2 * tig + 8) * 32 + n] : 0.f;
            float wb = (2 * tig + 9 < 10) ? W1[e * 320 + (2 * tig + 9) * 32 + n] : 0.f;
            split_pair(wa, wb, b1h[nt][1], b1l[nt][1]);
        }
        // L2
        #pragma unroll
        for (int kt = 0; kt < 2; kt++) {
            int k0 = kt * 16 + 2 * tig;
            float wa = W2[e * 1024 + k0 * 32 + n];
            float wb = W2[e * 1024 + (k0 + 1) * 32 + n];
            split_pair(wa, wb, b2h[nt][kt][0], b2l[nt][kt][0]);
            float wc = W2[e * 1024 + (k0 + 8) * 32 + n];
            float wd = W2[e * 1024 + (k0 + 9) * 32 + n];
            split_pair(wc, wd, b2h[nt][kt][1], b2l[nt][kt][1]);
        }
        int c0 = nt * 8 + 2 * tig;
        bias1[nt][0] = b1[e * 32 + c0];     bias1[nt][1] = b1[e * 32 + c0 + 1];
        bias2[nt][0] = b2[e * 32 + c0];     bias2[nt][1] = b2[e * 32 + c0 + 1];
        w3r[nt][0][0] = W3[(e * 32 + c0) * 2];
        w3r[nt][0][1] = W3[(e * 32 + c0) * 2 + 1];
        w3r[nt][1][0] = W3[(e * 32 + c0 + 1) * 2];
        w3r[nt][1][1] = W3[(e * 32 + c0 + 1) * 2 + 1];
    }
    const float b3e0 = b3[e * 2], b3e1 = b3[e * 2 + 1];
    __syncthreads();

    for (int tile = blockIdx.x; tile < NTILES; tile += gridDim.x) {
        const int tok = tile * 256 + tid;

        // ================= phase 1: x load, gate, staging =================
        float x[10];
        {
            const float2* xp = reinterpret_cast<const float2*>(X + (size_t)tok * 10);
            #pragma unroll
            for (int i = 0; i < 5; i++) { float2 v = xp[i]; x[2*i] = v.x; x[2*i+1] = v.y; }
        }

        float wsum;
        {
            u64 l2a[4];
            const float2* gb2p = (const float2*)(sf + FGB2);
            #pragma unroll
            for (int j = 0; j < 4; j++) l2a[j] = f2u(gb2p[j]);
            #pragma unroll 1
            for (int c = 0; c < 4; c++) {
                u64 acc[8];
                const float2* bp = (const float2*)(sf + FGB1 + c * 16);
                #pragma unroll
                for (int j = 0; j < 8; j++) acc[j] = f2u(bp[j]);
                #pragma unroll
                for (int k = 0; k < 10; k++) {
                    u64 m = pkdup(x[k]);
                    const float4* wr = (const float4*)(sf + FG1 + k * 64 + c * 16);
                    #pragma unroll
                    for (int j = 0; j < 4; j++) {
                        float4 w = wr[j];
                        acc[2*j]   = fma2(m, pk(w.x, w.y), acc[2*j]);
                        acc[2*j+1] = fma2(m, pk(w.z, w.w), acc[2*j+1]);
                    }
                }
                #pragma unroll
                for (int j = 0; j < 8; j++) {
                    const float4* g2r = (const float4*)(sf + FG2 + (c * 16 + 2 * j) * 8);
                    float4 ra0 = g2r[0], ra1 = g2r[1], rb0 = g2r[2], rb1_ = g2r[3];
                    float p, q; upk(acc[j], p, q);
                    p = fmaxf(p, 0.f); q = fmaxf(q, 0.f);
                    u64 mp = pkdup(p), mq = pkdup(q);
                    l2a[0] = fma2(mp, pk(ra0.x, ra0.y), l2a[0]);
                    l2a[1] = fma2(mp, pk(ra0.z, ra0.w), l2a[1]);
                    l2a[2] = fma2(mp, pk(ra1.x, ra1.y), l2a[2]);
                    l2a[3] = fma2(mp, pk(ra1.z, ra1.w), l2a[3]);
                    l2a[0] = fma2(mq, pk(rb0.x, rb0.y), l2a[0]);
                    l2a[1] = fma2(mq, pk(rb0.z, rb0.w), l2a[1]);
                    l2a[2] = fma2(mq, pk(rb1_.x, rb1_.y), l2a[2]);
                    l2a[3] = fma2(mq, pk(rb1_.z, rb1_.w), l2a[3]);
                }
            }
            float l[8];
            #pragma unroll
            for (int j = 0; j < 4; j++) upk(l2a[j], l[2*j], l[2*j+1]);
            float m = l[0];
            #pragma unroll
            for (int i = 1; i < 8; i++) m = fmaxf(m, l[i]);
            wsum = 0.f;
            float* wxp = reinterpret_cast<float*>(smem_raw + WX);
            #pragma unroll
            for (int i = 0; i < 8; i++) {
                float v = __expf(l[i] - m); wsum += v;
                wxp[i * 256 + tid] = v;
            }
        }

        // stage x split fragments: row = tid, [32B hi k0-15][32B lo][16B pad]
        {
            u32 xsh[8], xsl[8];
            #pragma unroll
            for (int i = 0; i < 5; i++)
                split_pair(x[2*i], x[2*i+1], xsh[i], xsl[i]);
            xsh[5] = xsh[6] = xsh[7] = 0u; xsl[5] = xsl[6] = xsl[7] = 0u;
            uint4* ph = reinterpret_cast<uint4*>(smem_raw + XB + tid * 80);
            ph[0] = make_uint4(xsh[0], xsh[1], xsh[2], xsh[3]);
            ph[1] = make_uint4(xsh[4], xsh[5], xsh[6], xsh[7]);
            uint4* pl = reinterpret_cast<uint4*>(smem_raw + XB + tid * 80 + 32);
            pl[0] = make_uint4(xsl[0], xsl[1], xsl[2], xsl[3]);
            pl[1] = make_uint4(xsl[4], xsl[5], xsl[6], xsl[7]);
        }
        __syncthreads();

        // ================= phase 2: expert GEMMs (warp = expert) =================
        {
            const float* wxp = reinterpret_cast<const float*>(smem_raw + WX);
            float2* fup = reinterpret_cast<float2*>(smem_raw + FU);
            #pragma unroll 1
            for (int mt = 0; mt < 16; mt++) {
                // x A-fragments via ldmatrix
                u32 ah[4], al[4];
                u32 addr = sbase + XB + (u32)(mt * 16 + (lane & 15)) * 80 + ((lane >> 4) << 4);
                ldm_x4(ah, addr);
                ldm_x4(al, addr + 32);

                // L1: 4 n-tiles, 3-pass split
                float d[4][4];
                #pragma unroll
                for (int nt = 0; nt < 4; nt++) {
                    d[nt][0] = d[nt][1] = d[nt][2] = d[nt][3] = 0.f;
                    mma16816(d[nt][0], d[nt][1], d[nt][2], d[nt][3],
                             ah[0], ah[1], ah[2], ah[3], b1h[nt][0], b1h[nt][1]);
                    mma16816(d[nt][0], d[nt][1], d[nt][2], d[nt][3],
                             ah[0], ah[1], ah[2], ah[3], b1l[nt][0], b1l[nt][1]);
                    mma16816(d[nt][0], d[nt][1], d[nt][2], d[nt][3],
                             al[0], al[1], al[2], al[3], b1h[nt][0], b1h[nt][1]);
                }
                // epilogue: bias+relu, split -> L2 A-fragments (register only)
                u32 a2h[2][4], a2l[2][4];
                #pragma unroll
                for (int nt = 0; nt < 4; nt++) {
                    float v0 = fmaxf(d[nt][0] + bias1[nt][0], 0.f);
                    float v1 = fmaxf(d[nt][1] + bias1[nt][1], 0.f);
                    float v2 = fmaxf(d[nt][2] + bias1[nt][0], 0.f);
                    float v3 = fmaxf(d[nt][3] + bias1[nt][1], 0.f);
                    int kt = nt >> 1, hf = (nt & 1) << 1;   // hf: 0 -> a0/a1, 2 -> a2/a3
                    split_pair(v0, v1, a2h[kt][hf],     a2l[kt][hf]);
                    split_pair(v2, v3, a2h[kt][hf + 1], a2l[kt][hf + 1]);
                }
                // L2: 4 n-tiles x (2 kt x 3 passes)
                float g[4][4];
                #pragma unroll
                for (int nt = 0; nt < 4; nt++) {
                    g[nt][0] = g[nt][1] = g[nt][2] = g[nt][3] = 0.f;
                    mma16816(g[nt][0], g[nt][1], g[nt][2], g[nt][3],
                             a2h[0][0], a2h[0][1], a2h[0][2], a2h[0][3],
                             b2h[nt][0][0], b2h[nt][0][1]);
                    mma16816(g[nt][0], g[nt][1], g[nt][2], g[nt][3],
                             a2h[0][0], a2h[0][1], a2h[0][2], a2h[0][3],
                             b2l[nt][0][0], b2l[nt][0][1]);
                    mma16816(g[nt][0], g[nt][1], g[nt][2], g[nt][3],
                             a2l[0][0], a2l[0][1], a2l[0][2], a2l[0][3],
                             b2h[nt][0][0], b2h[nt][0][1]);
                    mma16816(g[nt][0], g[nt][1], g[nt][2], g[nt][3],
                             a2h[1][0], a2h[1][1], a2h[1][2], a2h[1][3],
                             b2h[nt][1][0], b2h[nt][1][1]);
                    mma16816(g[nt][0], g[nt][1], g[nt][2], g[nt][3],
                             a2h[1][0], a2h[1][1], a2h[1][2], a2h[1][3],
                             b2l[nt][1][0], b2l[nt][1][1]);
                    mma16816(g[nt][0], g[nt][1], g[nt][2], g[nt][3],
                             a2l[1][0], a2l[1][1], a2l[1][2], a2l[1][3],
                             b2h[nt][1][0], b2h[nt][1][1]);
                }
                // epilogue: bias+relu, fold L3 (32->2)
                float oA0 = 0.f, oA1 = 0.f, oB0 = 0.f, oB1 = 0.f;
                #pragma unroll
                for (int nt = 0; nt < 4; nt++) {
                    float v0 = fmaxf(g[nt][0] + bias2[nt][0], 0.f);
                    float v1 = fmaxf(g[nt][1] + bias2[nt][1], 0.f);
                    float v2 = fmaxf(g[nt][2] + bias2[nt][0], 0.f);
                    float v3 = fmaxf(g[nt][3] + bias2[nt][1], 0.f);
                    oA0 += v0 * w3r[nt][0][0] + v1 * w3r[nt][1][0];
                    oA1 += v0 * w3r[nt][0][1] + v1 * w3r[nt][1][1];
                    oB0 += v2 * w3r[nt][0][0] + v3 * w3r[nt][1][0];
                    oB1 += v2 * w3r[nt][0][1] + v3 * w3r[nt][1][1];
                }
                oA0 += __shfl_xor_sync(0xFFFFFFFFu, oA0, 1);
                oA0 += __shfl_xor_sync(0xFFFFFFFFu, oA0, 2);
                oA1 += __shfl_xor_sync(0xFFFFFFFFu, oA1, 1);
                oA1 += __shfl_xor_sync(0xFFFFFFFFu, oA1, 2);
                oB0 += __shfl_xor_sync(0xFFFFFFFFu, oB0, 1);
                oB0 += __shfl_xor_sync(0xFFFFFFFFu, oB0, 2);
                oB1 += __shfl_xor_sync(0xFFFFFFFFu, oB1, 1);
                oB1 += __shfl_xor_sync(0xFFFFFFFFu, oB1, 2);
                if (tig < 2) {
                    int tk = mt * 16 + grp + 8 * tig;
                    float u0 = tig ? oB0 : oA0;
                    float u1 = tig ? oB1 : oA1;
                    float s0 = tanh_acc(u0 + b3e0);
                    float s1 = tanh_acc(u1 + b3e1);
                    float wv = wxp[e * 256 + tk];
                    fup[e * 256 + tk] = make_float2(wv * s0, wv * s1);
                }
            }
        }
        __syncthreads();

        // ================= phase 3: refine (thread = token) =================
        float rin[12];
        {
            const float2* fup = reinterpret_cast<const float2*>(smem_raw + FU);
            float f0 = 0.f, f1 = 0.f;
            #pragma unroll
            for (int q = 0; q < 8; q++) {
                float2 v = fup[q * 256 + tid];
                f0 += v.x; f1 += v.y;
            }
            float inv = 1.0f / wsum;
            rin[0] = f0 * inv; rin[1] = f1 * inv;
            #pragma unroll
            for (int i = 0; i < 10; i++) rin[2 + i] = x[i];
        }
        u64 racc = f2u(*reinterpret_cast<const float2*>(sf + FRB2));
        #pragma unroll 1
        for (int c = 0; c < 4; c++) {
            u64 acc[8];
            const float2* bp = (const float2*)(sf + FRB1 + c * 16);
            #pragma unroll
            for (int j = 0; j < 8; j++) acc[j] = f2u(bp[j]);
            #pragma unroll
            for (int k = 0; k < 12; k++) {
                u64 m = pkdup(rin[k]);
                const float4* wr = (const float4*)(sf + FR1 + k * 64 + c * 16);
                #pragma unroll
                for (int j = 0; j < 4; j++) {
                    float4 w = wr[j];
                    acc[2*j]   = fma2(m, pk(w.x, w.y), acc[2*j]);
                    acc[2*j+1] = fma2(m, pk(w.z, w.w), acc[2*j+1]);
                }
            }
            #pragma unroll
            for (int j = 0; j < 8; j++) {
                const float2* r2 = (const float2*)(sf + FR2 + (c * 16 + 2 * j) * 2);
                u64 we = f2u(r2[0]), wo = f2u(r2[1]);
                float p, q; upk(acc[j], p, q);
                p = fmaxf(p, 0.f); q = fmaxf(q, 0.f);
                racc = fma2(pkdup(p), we, racc);
                racc = fma2(pkdup(q), wo, racc);
            }
        }
        {
            float y0, y1; upk(racc, y0, y1);
            reinterpret_cast<float2*>(out)[tok] =
                make_float2(tanh_acc(y0), tanh_acc(y1));
        }
    }
}

extern "C" void kernel_launch(void* const* d_in, const int* in_sizes, int n_in,
                              void* d_out, int out_size)
{
    (void)in_sizes; (void)n_in; (void)out_size;
    const float* X   = (const float*)d_in[0];
    const float* W1  = (const float*)d_in[1];
    const float* b1  = (const float*)d_in[2];
    const float* W2  = (const float*)d_in[3];
    const float* b2  = (const float*)d_in[4];
    const float* W3  = (const float*)d_in[5];
    const float* b3  = (const float*)d_in[6];
    const float* G1  = (const float*)d_in[7];
    const float* gb1 = (const float*)d_in[8];
    const float* G2  = (const float*)d_in[9];
    const float* gb2 = (const float*)d_in[10];
    const float* R1  = (const float*)d_in[11];
    const float* rb1 = (const float*)d_in[12];
    const float* R2  = (const float*)d_in[13];
    const float* rb2 = (const float*)d_in[14];

    cudaFuncSetAttribute(moe_r6_kernel,
                         cudaFuncAttributeMaxDynamicSharedMemorySize, SMEM_TOTAL);

    moe_r6_kernel<<<GRID, 256, SMEM_TOTAL>>>(
        X, W1, b1, W2, b2, W3, b3, G1, gb1, G2, gb2, R1, rb1, R2, rb2,
        (float*)d_out);
}

// round 7
// speedup vs baseline: 1.6235x; 1.0012x over previous
#include <cuda_runtime.h>
#include <cuda_bf16.h>
#include <cstdint>

// Round 6: expert-specialized warps; all expert weights as register-resident
// mma.sync B-fragments; L1 D-frag reused in-register as L2 A-frag (no h1 SMEM).
// CTA = 256 threads = 8 warps (warp e = expert e), tile = 256 tokens.

#define NTILES 4096
#define GRID   592

typedef unsigned long long u64;
typedef unsigned int u32;

// ---------------- scalar fp32x2 helpers ----------------
__device__ __forceinline__ u64 pk(float a, float b) {
    u64 r; asm("mov.b64 %0,{%1,%2};" : "=l"(r) : "f"(a), "f"(b)); return r;
}
__device__ __forceinline__ u64 pkdup(float a) { return pk(a, a); }
__device__ __forceinline__ void upk(u64 v, float& a, float& b) {
    asm("mov.b64 {%0,%1},%2;" : "=f"(a), "=f"(b) : "l"(v));
}
__device__ __forceinline__ u64 fma2(u64 a, u64 b, u64 c) {
    u64 d; asm("fma.rn.f32x2 %0,%1,%2,%3;" : "=l"(d) : "l"(a), "l"(b), "l"(c)); return d;
}
__device__ __forceinline__ u64 f2u(float2 v) { return pk(v.x, v.y); }

// ---------------- bf16 helpers ----------------
__device__ __forceinline__ u32 fbits(float f) { return __float_as_uint(f); }
__device__ __forceinline__ u32 prmt_hi(u32 a, u32 b) {           // lo=hi(a), hi=hi(b)
    u32 d; asm("prmt.b32 %0,%1,%2,0x7632;" : "=r"(d) : "r"(a), "r"(b)); return d;
}
__device__ __forceinline__ u32 cvt_bf2(float lov, float hiv) {   // lo=rn(lov), hi=rn(hiv)
    u32 d; asm("cvt.rn.bf16x2.f32 %0,%1,%2;" : "=r"(d) : "f"(hiv), "f"(lov)); return d;
}
__device__ __forceinline__ float truncf16(float v) {
    return __uint_as_float(fbits(v) & 0xFFFF0000u);
}
__device__ __forceinline__ float tanh_acc(float v) {
    float e = __expf(2.0f * v);
    return 1.0f - __fdividef(2.0f, e + 1.0f);
}

// ---------------- mma / ldmatrix ----------------
__device__ __forceinline__ void mma16816(float& d0, float& d1, float& d2, float& d3,
                                         u32 a0, u32 a1, u32 a2, u32 a3,
                                         u32 b0, u32 b1) {
    asm volatile("mma.sync.aligned.m16n8k16.row.col.f32.bf16.bf16.f32 "
                 "{%0,%1,%2,%3},{%4,%5,%6,%7},{%8,%9},{%0,%1,%2,%3};"
                 : "+f"(d0), "+f"(d1), "+f"(d2), "+f"(d3)
                 : "r"(a0), "r"(a1), "r"(a2), "r"(a3), "r"(b0), "r"(b1));
}
__device__ __forceinline__ void ldm_x4(u32* r, u32 addr) {
    asm volatile("ldmatrix.sync.aligned.m8n8.x4.shared.b16 {%0,%1,%2,%3}, [%4];"
                 : "=r"(r[0]), "=r"(r[1]), "=r"(r[2]), "=r"(r[3]) : "r"(addr));
}
__device__ __forceinline__ u32 smem_to_u32(const void* p) {
    u32 a;
    asm("{ .reg .u64 t; cvta.to.shared.u64 t, %1; cvt.u32.u64 %0, t; }" : "=r"(a) : "l"(p));
    return a;
}

// split a weight into (hi-pair, lo-pair) packed bf16x2 from two floats
__device__ __forceinline__ void split_pair(float a, float b, u32& hi, u32& lo) {
    hi = prmt_hi(fbits(a), fbits(b));
    lo = cvt_bf2(a - truncf16(a), b - truncf16(b));
}

// ---------------- SMEM layout (bytes) ----------------
#define XB 0            // x fragments: 256 rows x 80B (32B hi, 32B lo, 16B pad)
#define WX 20480        // wexp [8 experts][256 tok] f32
#define FU 28672        // fused partials [8][256] float2
#define SF 45056        // fp32 gate/refine weights
// sf offsets (floats)
#define FG1  0
#define FGB1 640
#define FG2  704
#define FGB2 1216
#define FR1  1224
#define FRB1 1992
#define FR2  2056
#define FRB2 2184
#define SF_FLOATS 2186
#define SMEM_TOTAL (SF + SF_FLOATS * 4 + 8)

extern __shared__ char smem_raw[];

__global__ void __launch_bounds__(256, 1)
moe_r6_kernel(const float* __restrict__ X,
              const float* __restrict__ W1, const float* __restrict__ b1,
              const float* __restrict__ W2, const float* __restrict__ b2,
              const float* __restrict__ W3, const float* __restrict__ b3,
              const float* __restrict__ G1, const float* __restrict__ gb1,
              const float* __restrict__ G2, const float* __restrict__ gb2,
              const float* __restrict__ R1, const float* __restrict__ rb1,
              const float* __restrict__ R2, const float* __restrict__ rb2,
              float* __restrict__ out)
{
    const int tid  = threadIdx.x;
    const int wid  = tid >> 5;     // = expert id
    const int lane = tid & 31;
    const int grp  = lane >> 2;
    const int tig  = lane & 3;
    float* sf = reinterpret_cast<float*>(smem_raw + SF);
    const u32 sbase = smem_to_u32(smem_raw);

    // ---- stage gate/refine fp32 weights into SMEM ----
    for (int i = tid; i < 640; i += 256) sf[FG1 + i]  = G1[i];
    for (int i = tid; i < 64;  i += 256) sf[FGB1 + i] = gb1[i];
    for (int i = tid; i < 512; i += 256) sf[FG2 + i]  = G2[i];
    for (int i = tid; i < 8;   i += 256) sf[FGB2 + i] = gb2[i];
    for (int i = tid; i < 768; i += 256) sf[FR1 + i]  = R1[i];
    for (int i = tid; i < 64;  i += 256) sf[FRB1 + i] = rb1[i];
    for (int i = tid; i < 128; i += 256) sf[FR2 + i]  = R2[i];
    if (tid < 2) sf[FRB2 + tid] = rb2[tid];

    // ---- load this warp's expert weights into register fragments (one time) ----
    const int e = wid;
    u32 b1h[4][2], b1l[4][2];           // [nt][b0/b1]
    u32 b2h[4][2][2], b2l[4][2][2];     // [nt][kt][b0/b1]
    float bias1[4][2], bias2[4][2], w3r[4][2][2];
    #pragma unroll
    for (int nt = 0; nt < 4; nt++) {
        int n = nt * 8 + grp;
        // L1 b0: k = 2tig, 2tig+1 (< 8, always valid)
        {
            float wa = W1[e * 320 + (2 * tig)     * 32 + n];
            float wb = W1[e * 320 + (2 * tig + 1) * 32 + n];
            split_pair(wa, wb, b1h[nt][0], b1l[nt][0]);
        }
        // L1 b1: k = 2tig+8, 2tig+9 (valid only when < 10 -> tig==0)
        {
            float wa = (2 * tig + 8 < 10) ? W1[e * 320 + (2 * tig + 8) * 32 + n] : 0.f;
            float wb = (2 * tig + 9 < 10) ? W1[e * 320 + (2 * tig + 9) * 32 + n] : 0.f;
            split_pair(wa, wb, b1h[nt][1], b1l[nt][1]);
        }
        // L2
        #pragma unroll
        for (int kt = 0; kt < 2; kt++) {
            int k0 = kt * 16 + 2 * tig;
            float wa = W2[e * 1024 + k0 * 32 + n];
            float wb = W2[e * 1024 + (k0 + 1) * 32 + n];
            split_pair(wa, wb, b2h[nt][kt][0], b2l[nt][kt][0]);
            float wc = W2[e * 1024 + (k0 + 8) * 32 + n];
            float wd = W2[e * 1024 + (k0 + 9) * 32 + n];
            split_pair(wc, wd, b2h[nt][kt][1], b2l[nt][kt][1]);
        }
        int c0 = nt * 8 + 2 * tig;
        bias1[nt][0] = b1[e * 32 + c0];     bias1[nt][1] = b1[e * 32 + c0 + 1];
        bias2[nt][0] = b2[e * 32 + c0];     bias2[nt][1] = b2[e * 32 + c0 + 1];
        w3r[nt][0][0] = W3[(e * 32 + c0) * 2];
        w3r[nt][0][1] = W3[(e * 32 + c0) * 2 + 1];
        w3r[nt][1][0] = W3[(e * 32 + c0 + 1) * 2];
        w3r[nt][1][1] = W3[(e * 32 + c0 + 1) * 2 + 1];
    }
    const float b3e0 = b3[e * 2], b3e1 = b3[e * 2 + 1];
    __syncthreads();

    for (int tile = blockIdx.x; tile < NTILES; tile += gridDim.x) {
        const int tok = tile * 256 + tid;

        // ================= phase 1: x load, gate, staging =================
        float x[10];
        {
            const float2* xp = reinterpret_cast<const float2*>(X + (size_t)tok * 10);
            #pragma unroll
            for (int i = 0; i < 5; i++) { float2 v = xp[i]; x[2*i] = v.x; x[2*i+1] = v.y; }
        }

        float wsum;
        {
            u64 l2a[4];
            const float2* gb2p = (const float2*)(sf + FGB2);
            #pragma unroll
            for (int j = 0; j < 4; j++) l2a[j] = f2u(gb2p[j]);
            #pragma unroll 1
            for (int c = 0; c < 4; c++) {
                u64 acc[8];
                const float2* bp = (const float2*)(sf + FGB1 + c * 16);
                #pragma unroll
                for (int j = 0; j < 8; j++) acc[j] = f2u(bp[j]);
                #pragma unroll
                for (int k = 0; k < 10; k++) {
                    u64 m = pkdup(x[k]);
                    const float4* wr = (const float4*)(sf + FG1 + k * 64 + c * 16);
                    #pragma unroll
                    for (int j = 0; j < 4; j++) {
                        float4 w = wr[j];
                        acc[2*j]   = fma2(m, pk(w.x, w.y), acc[2*j]);
                        acc[2*j+1] = fma2(m, pk(w.z, w.w), acc[2*j+1]);
                    }
                }
                #pragma unroll
                for (int j = 0; j < 8; j++) {
                    const float4* g2r = (const float4*)(sf + FG2 + (c * 16 + 2 * j) * 8);
                    float4 ra0 = g2r[0], ra1 = g2r[1], rb0 = g2r[2], rb1_ = g2r[3];
                    float p, q; upk(acc[j], p, q);
                    p = fmaxf(p, 0.f); q = fmaxf(q, 0.f);
                    u64 mp = pkdup(p), mq = pkdup(q);
                    l2a[0] = fma2(mp, pk(ra0.x, ra0.y), l2a[0]);
                    l2a[1] = fma2(mp, pk(ra0.z, ra0.w), l2a[1]);
                    l2a[2] = fma2(mp, pk(ra1.x, ra1.y), l2a[2]);
                    l2a[3] = fma2(mp, pk(ra1.z, ra1.w), l2a[3]);
                    l2a[0] = fma2(mq, pk(rb0.x, rb0.y), l2a[0]);
                    l2a[1] = fma2(mq, pk(rb0.z, rb0.w), l2a[1]);
                    l2a[2] = fma2(mq, pk(rb1_.x, rb1_.y), l2a[2]);
                    l2a[3] = fma2(mq, pk(rb1_.z, rb1_.w), l2a[3]);
                }
            }
            float l[8];
            #pragma unroll
            for (int j = 0; j < 4; j++) upk(l2a[j], l[2*j], l[2*j+1]);
            float m = l[0];
            #pragma unroll
            for (int i = 1; i < 8; i++) m = fmaxf(m, l[i]);
            wsum = 0.f;
            float* wxp = reinterpret_cast<float*>(smem_raw + WX);
            #pragma unroll
            for (int i = 0; i < 8; i++) {
                float v = __expf(l[i] - m); wsum += v;
                wxp[i * 256 + tid] = v;
            }
        }

        // stage x split fragments: row = tid, [32B hi k0-15][32B lo][16B pad]
        {
            u32 xsh[8], xsl[8];
            #pragma unroll
            for (int i = 0; i < 5; i++)
                split_pair(x[2*i], x[2*i+1], xsh[i], xsl[i]);
            xsh[5] = xsh[6] = xsh[7] = 0u; xsl[5] = xsl[6] = xsl[7] = 0u;
            uint4* ph = reinterpret_cast<uint4*>(smem_raw + XB + tid * 80);
            ph[0] = make_uint4(xsh[0], xsh[1], xsh[2], xsh[3]);
            ph[1] = make_uint4(xsh[4], xsh[5], xsh[6], xsh[7]);
            uint4* pl = reinterpret_cast<uint4*>(smem_raw + XB + tid * 80 + 32);
            pl[0] = make_uint4(xsl[0], xsl[1], xsl[2], xsl[3]);
            pl[1] = make_uint4(xsl[4], xsl[5], xsl[6], xsl[7]);
        }
        __syncthreads();

        // ================= phase 2: expert GEMMs (warp = expert) =================
        {
            const float* wxp = reinterpret_cast<const float*>(smem_raw + WX);
            float2* fup = reinterpret_cast<float2*>(smem_raw + FU);
            #pragma unroll 1
            for (int mt = 0; mt < 16; mt++) {
                // x A-fragments via ldmatrix
                u32 ah[4], al[4];
                u32 addr = sbase + XB + (u32)(mt * 16 + (lane & 15)) * 80 + ((lane >> 4) << 4);
                ldm_x4(ah, addr);
                ldm_x4(al, addr + 32);

                // L1: 4 n-tiles, 3-pass split
                float d[4][4];
                #pragma unroll
                for (int nt = 0; nt < 4; nt++) {
                    d[nt][0] = d[nt][1] = d[nt][2] = d[nt][3] = 0.f;
                    mma16816(d[nt][0], d[nt][1], d[nt][2], d[nt][3],
                             ah[0], ah[1], ah[2], ah[3], b1h[nt][0], b1h[nt][1]);
                    mma16816(d[nt][0], d[nt][1], d[nt][2], d[nt][3],
                             ah[0], ah[1], ah[2], ah[3], b1l[nt][0], b1l[nt][1]);
                    mma16816(d[nt][0], d[nt][1], d[nt][2], d[nt][3],
                             al[0], al[1], al[2], al[3], b1h[nt][0], b1h[nt][1]);
                }
                // epilogue: bias+relu, split -> L2 A-fragments (register only)
                u32 a2h[2][4], a2l[2][4];
                #pragma unroll
                for (int nt = 0; nt < 4; nt++) {
                    float v0 = fmaxf(d[nt][0] + bias1[nt][0], 0.f);
                    float v1 = fmaxf(d[nt][1] + bias1[nt][1], 0.f);
                    float v2 = fmaxf(d[nt][2] + bias1[nt][0], 0.f);
                    float v3 = fmaxf(d[nt][3] + bias1[nt][1], 0.f);
                    int kt = nt >> 1, hf = (nt & 1) << 1;   // hf: 0 -> a0/a1, 2 -> a2/a3
                    split_pair(v0, v1, a2h[kt][hf],     a2l[kt][hf]);
                    split_pair(v2, v3, a2h[kt][hf + 1], a2l[kt][hf + 1]);
                }
                // L2: 4 n-tiles x (2 kt x 3 passes)
                float g[4][4];
                #pragma unroll
                for (int nt = 0; nt < 4; nt++) {
                    g[nt][0] = g[nt][1] = g[nt][2] = g[nt][3] = 0.f;
                    mma16816(g[nt][0], g[nt][1], g[nt][2], g[nt][3],
                             a2h[0][0], a2h[0][1], a2h[0][2], a2h[0][3],
                             b2h[nt][0][0], b2h[nt][0][1]);
                    mma16816(g[nt][0], g[nt][1], g[nt][2], g[nt][3],
                             a2h[0][0], a2h[0][1], a2h[0][2], a2h[0][3],
                             b2l[nt][0][0], b2l[nt][0][1]);
                    mma16816(g[nt][0], g[nt][1], g[nt][2], g[nt][3],
                             a2l[0][0], a2l[0][1], a2l[0][2], a2l[0][3],
                             b2h[nt][0][0], b2h[nt][0][1]);
                    mma16816(g[nt][0], g[nt][1], g[nt][2], g[nt][3],
                             a2h[1][0], a2h[1][1], a2h[1][2], a2h[1][3],
                             b2h[nt][1][0], b2h[nt][1][1]);
                    mma16816(g[nt][0], g[nt][1], g[nt][2], g[nt][3],
                             a2h[1][0], a2h[1][1], a2h[1][2], a2h[1][3],
                             b2l[nt][1][0], b2l[nt][1][1]);
                    mma16816(g[nt][0], g[nt][1], g[nt][2], g[nt][3],
                             a2l[1][0], a2l[1][1], a2l[1][2], a2l[1][3],
                             b2h[nt][1][0], b2h[nt][1][1]);
                }
                // epilogue: bias+relu, fold L3 (32->2)
                float oA0 = 0.f, oA1 = 0.f, oB0 = 0.f, oB1 = 0.f;
                #pragma unroll
                for (int nt = 0; nt < 4; nt++) {
                    float v0 = fmaxf(g[nt][0] + bias2[nt][0], 0.f);
                    float v1 = fmaxf(g[nt][1] + bias2[nt][1], 0.f);
                    float v2 = fmaxf(g[nt][2] + bias2[nt][0], 0.f);
                    float v3 = fmaxf(g[nt][3] + bias2[nt][1], 0.f);
                    oA0 += v0 * w3r[nt][0][0] + v1 * w3r[nt][1][0];
                    oA1 += v0 * w3r[nt][0][1] + v1 * w3r[nt][1][1];
                    oB0 += v2 * w3r[nt][0][0] + v3 * w3r[nt][1][0];
                    oB1 += v2 * w3r[nt][0][1] + v3 * w3r[nt][1][1];
                }
                oA0 += __shfl_xor_sync(0xFFFFFFFFu, oA0, 1);
                oA0 += __shfl_xor_sync(0xFFFFFFFFu, oA0, 2);
                oA1 += __shfl_xor_sync(0xFFFFFFFFu, oA1, 1);
                oA1 += __shfl_xor_sync(0xFFFFFFFFu, oA1, 2);
                oB0 += __shfl_xor_sync(0xFFFFFFFFu, oB0, 1);
                oB0 += __shfl_xor_sync(0xFFFFFFFFu, oB0, 2);
                oB1 += __shfl_xor_sync(0xFFFFFFFFu, oB1, 1);
                oB1 += __shfl_xor_sync(0xFFFFFFFFu, oB1, 2);
                if (tig < 2) {
                    int tk = mt * 16 + grp + 8 * tig;
                    float u0 = tig ? oB0 : oA0;
                    float u1 = tig ? oB1 : oA1;
                    float s0 = tanh_acc(u0 + b3e0);
                    float s1 = tanh_acc(u1 + b3e1);
                    float wv = wxp[e * 256 + tk];
                    fup[e * 256 + tk] = make_float2(wv * s0, wv * s1);
                }
            }
        }
        __syncthreads();

        // ================= phase 3: refine (thread = token) =================
        float rin[12];
        {
            const float2* fup = reinterpret_cast<const float2*>(smem_raw + FU);
            float f0 = 0.f, f1 = 0.f;
            #pragma unroll
            for (int q = 0; q < 8; q++) {
                float2 v = fup[q * 256 + tid];
                f0 += v.x; f1 += v.y;
            }
            float inv = 1.0f / wsum;
            rin[0] = f0 * inv; rin[1] = f1 * inv;
            #pragma unroll
            for (int i = 0; i < 10; i++) rin[2 + i] = x[i];
        }
        u64 racc = f2u(*reinterpret_cast<const float2*>(sf + FRB2));
        #pragma unroll 1
        for (int c = 0; c < 4; c++) {
            u64 acc[8];
            const float2* bp = (const float2*)(sf + FRB1 + c * 16);
            #pragma unroll
            for (int j = 0; j < 8; j++) acc[j] = f2u(bp[j]);
            #pragma unroll
            for (int k = 0; k < 12; k++) {
                u64 m = pkdup(rin[k]);
                const float4* wr = (const float4*)(sf + FR1 + k * 64 + c * 16);
                #pragma unroll
                for (int j = 0; j < 4; j++) {
                    float4 w = wr[j];
                    acc[2*j]   = fma2(m, pk(w.x, w.y), acc[2*j]);
                    acc[2*j+1] = fma2(m, pk(w.z, w.w), acc[2*j+1]);
                }
            }
            #pragma unroll
            for (int j = 0; j < 8; j++) {
                const float2* r2 = (const float2*)(sf + FR2 + (c * 16 + 2 * j) * 2);
                u64 we = f2u(r2[0]), wo = f2u(r2[1]);
                float p, q; upk(acc[j], p, q);
                p = fmaxf(p, 0.f); q = fmaxf(q, 0.f);
                racc = fma2(pkdup(p), we, racc);
                racc = fma2(pkdup(q), wo, racc);
            }
        }
        {
            float y0, y1; upk(racc, y0, y1);
            reinterpret_cast<float2*>(out)[tok] =
                make_float2(tanh_acc(y0), tanh_acc(y1));
        }
    }
}

extern "C" void kernel_launch(void* const* d_in, const int* in_sizes, int n_in,
                              void* d_out, int out_size)
{
    (void)in_sizes; (void)n_in; (void)out_size;
    const float* X   = (const float*)d_in[0];
    const float* W1  = (const float*)d_in[1];
    const float* b1  = (const float*)d_in[2];
    const float* W2  = (const float*)d_in[3];
    const float* b2  = (const float*)d_in[4];
    const float* W3  = (const float*)d_in[5];
    const float* b3  = (const float*)d_in[6];
    const float* G1  = (const float*)d_in[7];
    const float* gb1 = (const float*)d_in[8];
    const float* G2  = (const float*)d_in[9];
    const float* gb2 = (const float*)d_in[10];
    const float* R1  = (const float*)d_in[11];
    const float* rb1 = (const float*)d_in[12];
    const float* R2  = (const float*)d_in[13];
    const float* rb2 = (const float*)d_in[14];

    cudaFuncSetAttribute(moe_r6_kernel,
                         cudaFuncAttributeMaxDynamicSharedMemorySize, SMEM_TOTAL);

    moe_r6_kernel<<<GRID, 256, SMEM_TOTAL>>>(
        X, W1, b1, W2, b2, W3, b3, G1, gb1, G2, gb2, R1, rb1, R2, rb2,
        (float*)d_out);
}

// round 8
// speedup vs baseline: 1.7970x; 1.1069x over previous
#include <cuda_runtime.h>
#include <cuda_bf16.h>
#include <cstdint>

// Round 8: R7 design + 2 CTAs/SM. Loop-invariant L1-fragments/biases/W3 moved
// to per-lane SMEM (conflict-free LDS.128, stride 208B) to force regs <= 128.
// CTA = 256 threads = 8 warps (warp e = expert e), tile = 256 tokens.

#define NTILES 4096
#define GRID   592

typedef unsigned long long u64;
typedef unsigned int u32;

// ---------------- scalar fp32x2 helpers ----------------
__device__ __forceinline__ u64 pk(float a, float b) {
    u64 r; asm("mov.b64 %0,{%1,%2};" : "=l"(r) : "f"(a), "f"(b)); return r;
}
__device__ __forceinline__ u64 pkdup(float a) { return pk(a, a); }
__device__ __forceinline__ void upk(u64 v, float& a, float& b) {
    asm("mov.b64 {%0,%1},%2;" : "=f"(a), "=f"(b) : "l"(v));
}
__device__ __forceinline__ u64 fma2(u64 a, u64 b, u64 c) {
    u64 d; asm("fma.rn.f32x2 %0,%1,%2,%3;" : "=l"(d) : "l"(a), "l"(b), "l"(c)); return d;
}
__device__ __forceinline__ u64 f2u(float2 v) { return pk(v.x, v.y); }

// ---------------- bf16 helpers ----------------
__device__ __forceinline__ u32 fbits(float f) { return __float_as_uint(f); }
__device__ __forceinline__ u32 prmt_hi(u32 a, u32 b) {           // lo=hi(a), hi=hi(b)
    u32 d; asm("prmt.b32 %0,%1,%2,0x7632;" : "=r"(d) : "r"(a), "r"(b)); return d;
}
__device__ __forceinline__ u32 cvt_bf2(float lov, float hiv) {   // lo=rn(lov), hi=rn(hiv)
    u32 d; asm("cvt.rn.bf16x2.f32 %0,%1,%2;" : "=r"(d) : "f"(hiv), "f"(lov)); return d;
}
__device__ __forceinline__ float truncf16(float v) {
    return __uint_as_float(fbits(v) & 0xFFFF0000u);
}
__device__ __forceinline__ float tanh_acc(float v) {
    float e = __expf(2.0f * v);
    return 1.0f - __fdividef(2.0f, e + 1.0f);
}

// ---------------- mma / ldmatrix ----------------
__device__ __forceinline__ void mma16816(float& d0, float& d1, float& d2, float& d3,
                                         u32 a0, u32 a1, u32 a2, u32 a3,
                                         u32 b0, u32 b1) {
    asm volatile("mma.sync.aligned.m16n8k16.row.col.f32.bf16.bf16.f32 "
                 "{%0,%1,%2,%3},{%4,%5,%6,%7},{%8,%9},{%0,%1,%2,%3};"
                 : "+f"(d0), "+f"(d1), "+f"(d2), "+f"(d3)
                 : "r"(a0), "r"(a1), "r"(a2), "r"(a3), "r"(b0), "r"(b1));
}
__device__ __forceinline__ void ldm_x4(u32* r, u32 addr) {
    asm volatile("ldmatrix.sync.aligned.m8n8.x4.shared.b16 {%0,%1,%2,%3}, [%4];"
                 : "=r"(r[0]), "=r"(r[1]), "=r"(r[2]), "=r"(r[3]) : "r"(addr));
}
__device__ __forceinline__ u32 smem_to_u32(const void* p) {
    u32 a;
    asm("{ .reg .u64 t; cvta.to.shared.u64 t, %1; cvt.u32.u64 %0, t; }" : "=r"(a) : "l"(p));
    return a;
}

// split a weight into (hi-pair, lo-pair) packed bf16x2 from two floats
__device__ __forceinline__ void split_pair(float a, float b, u32& hi, u32& lo) {
    hi = prmt_hi(fbits(a), fbits(b));
    lo = cvt_bf2(a - truncf16(a), b - truncf16(b));
}

// ---------------- SMEM layout (bytes) ----------------
#define XB 0            // x fragments: 256 rows x 80B (32B hi, 32B lo, 16B pad)
#define WX 20480        // wexp [8 experts][256 tok] f32                (8 KB)
#define FU 28672        // fused partials [8][256] float2               (16 KB)
#define WL 45056        // per-lane loop constants: 256 lanes x 208B    (53248 B)
#define SF 98304        // fp32 gate/refine weights
// sf offsets (floats)
#define FG1  0
#define FGB1 640
#define FG2  704
#define FGB2 1216
#define FR1  1224
#define FRB1 1992
#define FR2  2056
#define FRB2 2184
#define SF_FLOATS 2186
#define SMEM_TOTAL (SF + SF_FLOATS * 4 + 8)   // ~107056

extern __shared__ char smem_raw[];

__global__ void __launch_bounds__(256, 2)
moe_r8_kernel(const float* __restrict__ X,
              const float* __restrict__ W1, const float* __restrict__ b1,
              const float* __restrict__ W2, const float* __restrict__ b2,
              const float* __restrict__ W3, const float* __restrict__ b3,
              const float* __restrict__ G1, const float* __restrict__ gb1,
              const float* __restrict__ G2, const float* __restrict__ gb2,
              const float* __restrict__ R1, const float* __restrict__ rb1,
              const float* __restrict__ R2, const float* __restrict__ rb2,
              float* __restrict__ out)
{
    const int tid  = threadIdx.x;
    const int wid  = tid >> 5;     // = expert id
    const int lane = tid & 31;
    const int grp  = lane >> 2;
    const int tig  = lane & 3;
    float* sf = reinterpret_cast<float*>(smem_raw + SF);
    const u32 sbase = smem_to_u32(smem_raw);

    // ---- stage gate/refine fp32 weights into SMEM ----
    for (int i = tid; i < 640; i += 256) sf[FG1 + i]  = G1[i];
    for (int i = tid; i < 64;  i += 256) sf[FGB1 + i] = gb1[i];
    for (int i = tid; i < 512; i += 256) sf[FG2 + i]  = G2[i];
    for (int i = tid; i < 8;   i += 256) sf[FGB2 + i] = gb2[i];
    for (int i = tid; i < 768; i += 256) sf[FR1 + i]  = R1[i];
    for (int i = tid; i < 64;  i += 256) sf[FRB1 + i] = rb1[i];
    for (int i = tid; i < 128; i += 256) sf[FR2 + i]  = R2[i];
    if (tid < 2) sf[FRB2 + tid] = rb2[tid];

    // ---- build weight fragments: W2 splits stay in registers; the rest go
    //      to the per-lane SMEM constant buffer (reloaded each mt, LDS.128) ----
    const int e = wid;
    u32 b2h[4][2][2], b2l[4][2][2];     // [nt][kt][b0/b1]  (register resident)
    {
        u32 b1hf[4][2], b1lf[4][2];
        float bias1f[4][2], bias2f[4][2], w3f[4][2][2];
        #pragma unroll
        for (int nt = 0; nt < 4; nt++) {
            int n = nt * 8 + grp;
            {
                float wa = W1[e * 320 + (2 * tig)     * 32 + n];
                float wb = W1[e * 320 + (2 * tig + 1) * 32 + n];
                split_pair(wa, wb, b1hf[nt][0], b1lf[nt][0]);
            }
            {
                float wa = (2 * tig + 8 < 10) ? W1[e * 320 + (2 * tig + 8) * 32 + n] : 0.f;
                float wb = (2 * tig + 9 < 10) ? W1[e * 320 + (2 * tig + 9) * 32 + n] : 0.f;
                split_pair(wa, wb, b1hf[nt][1], b1lf[nt][1]);
            }
            #pragma unroll
            for (int kt = 0; kt < 2; kt++) {
                int k0 = kt * 16 + 2 * tig;
                float wa = W2[e * 1024 + k0 * 32 + n];
                float wb = W2[e * 1024 + (k0 + 1) * 32 + n];
                split_pair(wa, wb, b2h[nt][kt][0], b2l[nt][kt][0]);
                float wc = W2[e * 1024 + (k0 + 8) * 32 + n];
                float wd = W2[e * 1024 + (k0 + 9) * 32 + n];
                split_pair(wc, wd, b2h[nt][kt][1], b2l[nt][kt][1]);
            }
            int c0 = nt * 8 + 2 * tig;
            bias1f[nt][0] = b1[e * 32 + c0];  bias1f[nt][1] = b1[e * 32 + c0 + 1];
            bias2f[nt][0] = b2[e * 32 + c0];  bias2f[nt][1] = b2[e * 32 + c0 + 1];
            w3f[nt][0][0] = W3[(e * 32 + c0) * 2];
            w3f[nt][0][1] = W3[(e * 32 + c0) * 2 + 1];
            w3f[nt][1][0] = W3[(e * 32 + c0 + 1) * 2];
            w3f[nt][1][1] = W3[(e * 32 + c0 + 1) * 2 + 1];
        }
        uint4* p = reinterpret_cast<uint4*>(smem_raw + WL + (size_t)tid * 208);
        p[0]  = make_uint4(b1hf[0][0], b1hf[0][1], b1hf[1][0], b1hf[1][1]);
        p[1]  = make_uint4(b1hf[2][0], b1hf[2][1], b1hf[3][0], b1hf[3][1]);
        p[2]  = make_uint4(b1lf[0][0], b1lf[0][1], b1lf[1][0], b1lf[1][1]);
        p[3]  = make_uint4(b1lf[2][0], b1lf[2][1], b1lf[3][0], b1lf[3][1]);
        float4* q = reinterpret_cast<float4*>(p);
        q[4]  = make_float4(bias1f[0][0], bias1f[0][1], bias1f[1][0], bias1f[1][1]);
        q[5]  = make_float4(bias1f[2][0], bias1f[2][1], bias1f[3][0], bias1f[3][1]);
        q[6]  = make_float4(bias2f[0][0], bias2f[0][1], bias2f[1][0], bias2f[1][1]);
        q[7]  = make_float4(bias2f[2][0], bias2f[2][1], bias2f[3][0], bias2f[3][1]);
        q[8]  = make_float4(w3f[0][0][0], w3f[0][0][1], w3f[0][1][0], w3f[0][1][1]);
        q[9]  = make_float4(w3f[1][0][0], w3f[1][0][1], w3f[1][1][0], w3f[1][1][1]);
        q[10] = make_float4(w3f[2][0][0], w3f[2][0][1], w3f[2][1][0], w3f[2][1][1]);
        q[11] = make_float4(w3f[3][0][0], w3f[3][0][1], w3f[3][1][0], w3f[3][1][1]);
    }
    const float b3e0 = b3[e * 2], b3e1 = b3[e * 2 + 1];
    __syncthreads();

    for (int tile = blockIdx.x; tile < NTILES; tile += gridDim.x) {
        const int tok = tile * 256 + tid;

        // ================= phase 1: x load, gate, staging =================
        float x[10];
        {
            const float2* xp = reinterpret_cast<const float2*>(X + (size_t)tok * 10);
            #pragma unroll
            for (int i = 0; i < 5; i++) { float2 v = xp[i]; x[2*i] = v.x; x[2*i+1] = v.y; }
        }

        float wsum;
        {
            u64 l2a[4];
            const float2* gb2p = (const float2*)(sf + FGB2);
            #pragma unroll
            for (int j = 0; j < 4; j++) l2a[j] = f2u(gb2p[j]);
            #pragma unroll 1
            for (int c = 0; c < 4; c++) {
                u64 acc[8];
                const float2* bp = (const float2*)(sf + FGB1 + c * 16);
                #pragma unroll
                for (int j = 0; j < 8; j++) acc[j] = f2u(bp[j]);
                #pragma unroll
                for (int k = 0; k < 10; k++) {
                    u64 m = pkdup(x[k]);
                    const float4* wr = (const float4*)(sf + FG1 + k * 64 + c * 16);
                    #pragma unroll
                    for (int j = 0; j < 4; j++) {
                        float4 w = wr[j];
                        acc[2*j]   = fma2(m, pk(w.x, w.y), acc[2*j]);
                        acc[2*j+1] = fma2(m, pk(w.z, w.w), acc[2*j+1]);
                    }
                }
                #pragma unroll
                for (int j = 0; j < 8; j++) {
                    const float4* g2r = (const float4*)(sf + FG2 + (c * 16 + 2 * j) * 8);
                    float4 ra0 = g2r[0], ra1 = g2r[1], rb0 = g2r[2], rb1_ = g2r[3];
                    float p, q; upk(acc[j], p, q);
                    p = fmaxf(p, 0.f); q = fmaxf(q, 0.f);
                    u64 mp = pkdup(p), mq = pkdup(q);
                    l2a[0] = fma2(mp, pk(ra0.x, ra0.y), l2a[0]);
                    l2a[1] = fma2(mp, pk(ra0.z, ra0.w), l2a[1]);
                    l2a[2] = fma2(mp, pk(ra1.x, ra1.y), l2a[2]);
                    l2a[3] = fma2(mp, pk(ra1.z, ra1.w), l2a[3]);
                    l2a[0] = fma2(mq, pk(rb0.x, rb0.y), l2a[0]);
                    l2a[1] = fma2(mq, pk(rb0.z, rb0.w), l2a[1]);
                    l2a[2] = fma2(mq, pk(rb1_.x, rb1_.y), l2a[2]);
                    l2a[3] = fma2(mq, pk(rb1_.z, rb1_.w), l2a[3]);
                }
            }
            float l[8];
            #pragma unroll
            for (int j = 0; j < 4; j++) upk(l2a[j], l[2*j], l[2*j+1]);
            float m = l[0];
            #pragma unroll
            for (int i = 1; i < 8; i++) m = fmaxf(m, l[i]);
            wsum = 0.f;
            float* wxp = reinterpret_cast<float*>(smem_raw + WX);
            #pragma unroll
            for (int i = 0; i < 8; i++) {
                float v = __expf(l[i] - m); wsum += v;
                wxp[i * 256 + tid] = v;
            }
        }

        // stage x split fragments: row = tid, [32B hi k0-15][32B lo][16B pad]
        {
            u32 xsh[8], xsl[8];
            #pragma unroll
            for (int i = 0; i < 5; i++)
                split_pair(x[2*i], x[2*i+1], xsh[i], xsl[i]);
            xsh[5] = xsh[6] = xsh[7] = 0u; xsl[5] = xsl[6] = xsl[7] = 0u;
            uint4* ph = reinterpret_cast<uint4*>(smem_raw + XB + tid * 80);
            ph[0] = make_uint4(xsh[0], xsh[1], xsh[2], xsh[3]);
            ph[1] = make_uint4(xsh[4], xsh[5], xsh[6], xsh[7]);
            uint4* pl = reinterpret_cast<uint4*>(smem_raw + XB + tid * 80 + 32);
            pl[0] = make_uint4(xsl[0], xsl[1], xsl[2], xsl[3]);
            pl[1] = make_uint4(xsl[4], xsl[5], xsl[6], xsl[7]);
        }
        __syncthreads();

        // ================= phase 2: expert GEMMs (warp = expert) =================
        {
            const float* wxp = reinterpret_cast<const float*>(smem_raw + WX);
            float2* fup = reinterpret_cast<float2*>(smem_raw + FU);
            const uint4* lb = reinterpret_cast<const uint4*>(smem_raw + WL + (size_t)tid * 208);
            const float4* lbf = reinterpret_cast<const float4*>(lb);
            #pragma unroll 1
            for (int mt = 0; mt < 16; mt++) {
                // x A-fragments via ldmatrix
                u32 ah[4], al[4];
                u32 addr = sbase + XB + (u32)(mt * 16 + (lane & 15)) * 80 + ((lane >> 4) << 4);
                ldm_x4(ah, addr);
                ldm_x4(al, addr + 32);

                // L1 fragments from per-lane SMEM
                uint4 h0 = lb[0], h1 = lb[1], l0 = lb[2], l1 = lb[3];
                u32 b1hA[4][2] = {{h0.x,h0.y},{h0.z,h0.w},{h1.x,h1.y},{h1.z,h1.w}};
                u32 b1lA[4][2] = {{l0.x,l0.y},{l0.z,l0.w},{l1.x,l1.y},{l1.z,l1.w}};

                // L1: 4 n-tiles, 3-pass split
                float d[4][4];
                #pragma unroll
                for (int nt = 0; nt < 4; nt++) {
                    d[nt][0] = d[nt][1] = d[nt][2] = d[nt][3] = 0.f;
                    mma16816(d[nt][0], d[nt][1], d[nt][2], d[nt][3],
                             ah[0], ah[1], ah[2], ah[3], b1hA[nt][0], b1hA[nt][1]);
                    mma16816(d[nt][0], d[nt][1], d[nt][2], d[nt][3],
                             ah[0], ah[1], ah[2], ah[3], b1lA[nt][0], b1lA[nt][1]);
                    mma16816(d[nt][0], d[nt][1], d[nt][2], d[nt][3],
                             al[0], al[1], al[2], al[3], b1hA[nt][0], b1hA[nt][1]);
                }
                // epilogue: bias+relu, split -> L2 A-fragments (register only)
                float4 bb0 = lbf[4], bb1 = lbf[5];
                float bias1A[4][2] = {{bb0.x,bb0.y},{bb0.z,bb0.w},{bb1.x,bb1.y},{bb1.z,bb1.w}};
                u32 a2h[2][4], a2l[2][4];
                #pragma unroll
                for (int nt = 0; nt < 4; nt++) {
                    float v0 = fmaxf(d[nt][0] + bias1A[nt][0], 0.f);
                    float v1 = fmaxf(d[nt][1] + bias1A[nt][1], 0.f);
                    float v2 = fmaxf(d[nt][2] + bias1A[nt][0], 0.f);
                    float v3 = fmaxf(d[nt][3] + bias1A[nt][1], 0.f);
                    int kt = nt >> 1, hf = (nt & 1) << 1;
                    split_pair(v0, v1, a2h[kt][hf],     a2l[kt][hf]);
                    split_pair(v2, v3, a2h[kt][hf + 1], a2l[kt][hf + 1]);
                }
                // L2: 4 n-tiles x (2 kt x 3 passes)
                float g[4][4];
                #pragma unroll
                for (int nt = 0; nt < 4; nt++) {
                    g[nt][0] = g[nt][1] = g[nt][2] = g[nt][3] = 0.f;
                    mma16816(g[nt][0], g[nt][1], g[nt][2], g[nt][3],
                             a2h[0][0], a2h[0][1], a2h[0][2], a2h[0][3],
                             b2h[nt][0][0], b2h[nt][0][1]);
                    mma16816(g[nt][0], g[nt][1], g[nt][2], g[nt][3],
                             a2h[0][0], a2h[0][1], a2h[0][2], a2h[0][3],
                             b2l[nt][0][0], b2l[nt][0][1]);
                    mma16816(g[nt][0], g[nt][1], g[nt][2], g[nt][3],
                             a2l[0][0], a2l[0][1], a2l[0][2], a2l[0][3],
                             b2h[nt][0][0], b2h[nt][0][1]);
                    mma16816(g[nt][0], g[nt][1], g[nt][2], g[nt][3],
                             a2h[1][0], a2h[1][1], a2h[1][2], a2h[1][3],
                             b2h[nt][1][0], b2h[nt][1][1]);
                    mma16816(g[nt][0], g[nt][1], g[nt][2], g[nt][3],
                             a2h[1][0], a2h[1][1], a2h[1][2], a2h[1][3],
                             b2l[nt][1][0], b2l[nt][1][1]);
                    mma16816(g[nt][0], g[nt][1], g[nt][2], g[nt][3],
                             a2l[1][0], a2l[1][1], a2l[1][2], a2l[1][3],
                             b2h[nt][1][0], b2h[nt][1][1]);
                }
                // epilogue: bias+relu, fold L3 (32->2)
                float4 cb0 = lbf[6], cb1 = lbf[7];
                float bias2A[4][2] = {{cb0.x,cb0.y},{cb0.z,cb0.w},{cb1.x,cb1.y},{cb1.z,cb1.w}};
                float oA0 = 0.f, oA1 = 0.f, oB0 = 0.f, oB1 = 0.f;
                #pragma unroll
                for (int nt = 0; nt < 4; nt++) {
                    float4 w3v = lbf[8 + nt];
                    float v0 = fmaxf(g[nt][0] + bias2A[nt][0], 0.f);
                    float v1 = fmaxf(g[nt][1] + bias2A[nt][1], 0.f);
                    float v2 = fmaxf(g[nt][2] + bias2A[nt][0], 0.f);
                    float v3 = fmaxf(g[nt][3] + bias2A[nt][1], 0.f);
                    oA0 += v0 * w3v.x + v1 * w3v.z;
                    oA1 += v0 * w3v.y + v1 * w3v.w;
                    oB0 += v2 * w3v.x + v3 * w3v.z;
                    oB1 += v2 * w3v.y + v3 * w3v.w;
                }
                oA0 += __shfl_xor_sync(0xFFFFFFFFu, oA0, 1);
                oA0 += __shfl_xor_sync(0xFFFFFFFFu, oA0, 2);
                oA1 += __shfl_xor_sync(0xFFFFFFFFu, oA1, 1);
                oA1 += __shfl_xor_sync(0xFFFFFFFFu, oA1, 2);
                oB0 += __shfl_xor_sync(0xFFFFFFFFu, oB0, 1);
                oB0 += __shfl_xor_sync(0xFFFFFFFFu, oB0, 2);
                oB1 += __shfl_xor_sync(0xFFFFFFFFu, oB1, 1);
                oB1 += __shfl_xor_sync(0xFFFFFFFFu, oB1, 2);
                if (tig < 2) {
                    int tk = mt * 16 + grp + 8 * tig;
                    float u0 = tig ? oB0 : oA0;
                    float u1 = tig ? oB1 : oA1;
                    float s0 = tanh_acc(u0 + b3e0);
                    float s1 = tanh_acc(u1 + b3e1);
                    float wv = wxp[e * 256 + tk];
                    fup[e * 256 + tk] = make_float2(wv * s0, wv * s1);
                }
            }
        }
        __syncthreads();

        // ================= phase 3: refine (thread = token) =================
        float rin[12];
        {
            const float2* fup = reinterpret_cast<const float2*>(smem_raw + FU);
            float f0 = 0.f, f1 = 0.f;
            #pragma unroll
            for (int q = 0; q < 8; q++) {
                float2 v = fup[q * 256 + tid];
                f0 += v.x; f1 += v.y;
            }
            float inv = 1.0f / wsum;
            rin[0] = f0 * inv; rin[1] = f1 * inv;
            #pragma unroll
            for (int i = 0; i < 10; i++) rin[2 + i] = x[i];
        }
        u64 racc = f2u(*reinterpret_cast<const float2*>(sf + FRB2));
        #pragma unroll 1
        for (int c = 0; c < 4; c++) {
            u64 acc[8];
            const float2* bp = (const float2*)(sf + FRB1 + c * 16);
            #pragma unroll
            for (int j = 0; j < 8; j++) acc[j] = f2u(bp[j]);
            #pragma unroll
            for (int k = 0; k < 12; k++) {
                u64 m = pkdup(rin[k]);
                const float4* wr = (const float4*)(sf + FR1 + k * 64 + c * 16);
                #pragma unroll
                for (int j = 0; j < 4; j++) {
                    float4 w = wr[j];
                    acc[2*j]   = fma2(m, pk(w.x, w.y), acc[2*j]);
                    acc[2*j+1] = fma2(m, pk(w.z, w.w), acc[2*j+1]);
                }
            }
            #pragma unroll
            for (int j = 0; j < 8; j++) {
                const float2* r2 = (const float2*)(sf + FR2 + (c * 16 + 2 * j) * 2);
                u64 we = f2u(r2[0]), wo = f2u(r2[1]);
                float p, q; upk(acc[j], p, q);
                p = fmaxf(p, 0.f); q = fmaxf(q, 0.f);
                racc = fma2(pkdup(p), we, racc);
                racc = fma2(pkdup(q), wo, racc);
            }
        }
        {
            float y0, y1; upk(racc, y0, y1);
            reinterpret_cast<float2*>(out)[tok] =
                make_float2(tanh_acc(y0), tanh_acc(y1));
        }
    }
}

extern "C" void kernel_launch(void* const* d_in, const int* in_sizes, int n_in,
                              void* d_out, int out_size)
{
    (void)in_sizes; (void)n_in; (void)out_size;
    const float* X   = (const float*)d_in[0];
    const float* W1  = (const float*)d_in[1];
    const float* b1  = (const float*)d_in[2];
    const float* W2  = (const float*)d_in[3];
    const float* b2  = (const float*)d_in[4];
    const float* W3  = (const float*)d_in[5];
    const float* b3  = (const float*)d_in[6];
    const float* G1  = (const float*)d_in[7];
    const float* gb1 = (const float*)d_in[8];
    const float* G2  = (const float*)d_in[9];
    const float* gb2 = (const float*)d_in[10];
    const float* R1  = (const float*)d_in[11];
    const float* rb1 = (const float*)d_in[12];
    const float* R2  = (const float*)d_in[13];
    const float* rb2 = (const float*)d_in[14];

    cudaFuncSetAttribute(moe_r8_kernel,
                         cudaFuncAttributeMaxDynamicSharedMemorySize, SMEM_TOTAL);

    moe_r8_kernel<<<GRID, 256, SMEM_TOTAL>>>(
        X, W1, b1, W2, b2, W3, b3, G1, gb1, G2, gb2, R1, rb1, R2, rb2,
        (float*)d_out);
}

// round 9
// speedup vs baseline: 2.6200x; 1.4580x over previous
#include <cuda_runtime.h>
#include <cuda_fp16.h>
#include <cstdint>

// Round 9: single-pass fp16 mma (error budget allows: threshold 1e-3, predicted
// ~2e-5). Bias via mma C-operand. Expert-specialized warps, weights in regs.
// CTA = 256 threads = 8 warps (warp e = expert e), tile = 256 tokens.

#define NTILES 4096
#define GRID   592

typedef unsigned long long u64;
typedef unsigned int u32;

// ---------------- scalar fp32x2 helpers ----------------
__device__ __forceinline__ u64 pk(float a, float b) {
    u64 r; asm("mov.b64 %0,{%1,%2};" : "=l"(r) : "f"(a), "f"(b)); return r;
}
__device__ __forceinline__ u64 pkdup(float a) { return pk(a, a); }
__device__ __forceinline__ void upk(u64 v, float& a, float& b) {
    asm("mov.b64 {%0,%1},%2;" : "=f"(a), "=f"(b) : "l"(v));
}
__device__ __forceinline__ u64 fma2(u64 a, u64 b, u64 c) {
    u64 d; asm("fma.rn.f32x2 %0,%1,%2,%3;" : "=l"(d) : "l"(a), "l"(b), "l"(c)); return d;
}
__device__ __forceinline__ u64 f2u(float2 v) { return pk(v.x, v.y); }

// pack two floats to f16x2: low half = lo, high half = hi
__device__ __forceinline__ u32 f16pk(float lo, float hi) {
    u32 d; asm("cvt.rn.f16x2.f32 %0,%1,%2;" : "=r"(d) : "f"(hi), "f"(lo)); return d;
}
__device__ __forceinline__ float tanh_acc(float v) {
    float e = __expf(2.0f * v);
    return 1.0f - __fdividef(2.0f, e + 1.0f);
}

// ---------------- mma / ldmatrix ----------------
// D = A*B + {c0,c1,c0,c1}   (bias init, D != C)
__device__ __forceinline__ void mma_f16_c(float& d0, float& d1, float& d2, float& d3,
                                          u32 a0, u32 a1, u32 a2, u32 a3,
                                          u32 b0, u32 b1, float c0, float c1) {
    asm volatile("mma.sync.aligned.m16n8k16.row.col.f32.f16.f16.f32 "
                 "{%0,%1,%2,%3},{%4,%5,%6,%7},{%8,%9},{%10,%11,%10,%11};"
                 : "=f"(d0), "=f"(d1), "=f"(d2), "=f"(d3)
                 : "r"(a0), "r"(a1), "r"(a2), "r"(a3), "r"(b0), "r"(b1),
                   "f"(c0), "f"(c1));
}
// D += A*B
__device__ __forceinline__ void mma_f16_acc(float& d0, float& d1, float& d2, float& d3,
                                            u32 a0, u32 a1, u32 a2, u32 a3,
                                            u32 b0, u32 b1) {
    asm volatile("mma.sync.aligned.m16n8k16.row.col.f32.f16.f16.f32 "
                 "{%0,%1,%2,%3},{%4,%5,%6,%7},{%8,%9},{%0,%1,%2,%3};"
                 : "+f"(d0), "+f"(d1), "+f"(d2), "+f"(d3)
                 : "r"(a0), "r"(a1), "r"(a2), "r"(a3), "r"(b0), "r"(b1));
}
__device__ __forceinline__ void ldm_x4(u32* r, u32 addr) {
    asm volatile("ldmatrix.sync.aligned.m8n8.x4.shared.b16 {%0,%1,%2,%3}, [%4];"
                 : "=r"(r[0]), "=r"(r[1]), "=r"(r[2]), "=r"(r[3]) : "r"(addr));
}
__device__ __forceinline__ u32 smem_to_u32(const void* p) {
    u32 a;
    asm("{ .reg .u64 t; cvta.to.shared.u64 t, %1; cvt.u32.u64 %0, t; }" : "=r"(a) : "l"(p));
    return a;
}

// ---------------- SMEM layout (bytes) ----------------
#define XB  0        // x fp16 fragments: 256 rows x 48B (32B data, 16B pad)
#define WX  12288    // wexp [8 experts][256 tok] f32         (8 KB)
#define FU  20480    // fused partials [8][256] float2        (16 KB)
#define TB2 36864    // bias2 table [e][nt][tig] float2       (1 KB)
#define TW3 37888    // w3 table    [e][nt][tig] float4       (2 KB)
#define SF  39936    // fp32 gate/refine weights
// sf offsets (floats)
#define FG1  0
#define FGB1 640
#define FG2  704
#define FGB2 1216
#define FR1  1224
#define FRB1 1992
#define FR2  2056
#define FRB2 2184
#define SF_FLOATS 2186
#define SMEM_TOTAL (SF + SF_FLOATS * 4 + 8)   // ~48688

extern __shared__ char smem_raw[];

__global__ void __launch_bounds__(256, 2)
moe_r9_kernel(const float* __restrict__ X,
              const float* __restrict__ W1, const float* __restrict__ b1,
              const float* __restrict__ W2, const float* __restrict__ b2,
              const float* __restrict__ W3, const float* __restrict__ b3,
              const float* __restrict__ G1, const float* __restrict__ gb1,
              const float* __restrict__ G2, const float* __restrict__ gb2,
              const float* __restrict__ R1, const float* __restrict__ rb1,
              const float* __restrict__ R2, const float* __restrict__ rb2,
              float* __restrict__ out)
{
    const int tid  = threadIdx.x;
    const int wid  = tid >> 5;     // = expert id
    const int lane = tid & 31;
    const int grp  = lane >> 5 ? 0 : (lane >> 2);   // lane>>2 (0..7)
    const int tig  = lane & 3;
    float* sf = reinterpret_cast<float*>(smem_raw + SF);
    const u32 sbase = smem_to_u32(smem_raw);

    // ---- stage gate/refine fp32 weights into SMEM ----
    for (int i = tid; i < 640; i += 256) sf[FG1 + i]  = G1[i];
    for (int i = tid; i < 64;  i += 256) sf[FGB1 + i] = gb1[i];
    for (int i = tid; i < 512; i += 256) sf[FG2 + i]  = G2[i];
    for (int i = tid; i < 8;   i += 256) sf[FGB2 + i] = gb2[i];
    for (int i = tid; i < 768; i += 256) sf[FR1 + i]  = R1[i];
    for (int i = tid; i < 64;  i += 256) sf[FRB1 + i] = rb1[i];
    for (int i = tid; i < 128; i += 256) sf[FR2 + i]  = R2[i];
    if (tid < 2) sf[FRB2 + tid] = rb2[tid];

    // ---- broadcast tables for bias2 / W3 (indexed [e][nt][tig]) ----
    if (tid < 128) {
        int te = tid >> 4, tn = (tid >> 2) & 3, tg = tid & 3;
        int c0 = tn * 8 + 2 * tg;
        *reinterpret_cast<float2*>(smem_raw + TB2 + tid * 8) =
            make_float2(b2[te * 32 + c0], b2[te * 32 + c0 + 1]);
        *reinterpret_cast<float4*>(smem_raw + TW3 + tid * 16) =
            make_float4(W3[(te * 32 + c0) * 2],     W3[(te * 32 + c0) * 2 + 1],
                        W3[(te * 32 + c0 + 1) * 2], W3[(te * 32 + c0 + 1) * 2 + 1]);
    }

    // ---- register-resident fp16 weight fragments for this warp's expert ----
    const int e = wid;
    u32 b1f[4][2];            // [nt][b0/b1]
    u32 b2f[4][2][2];         // [nt][kt][b0/b1]
    float bias1[4][2];
    #pragma unroll
    for (int nt = 0; nt < 4; nt++) {
        int n = nt * 8 + grp;
        b1f[nt][0] = f16pk(W1[e * 320 + (2 * tig) * 32 + n],
                           W1[e * 320 + (2 * tig + 1) * 32 + n]);
        {
            float wa = (2 * tig + 8 < 10) ? W1[e * 320 + (2 * tig + 8) * 32 + n] : 0.f;
            float wb = (2 * tig + 9 < 10) ? W1[e * 320 + (2 * tig + 9) * 32 + n] : 0.f;
            b1f[nt][1] = f16pk(wa, wb);
        }
        #pragma unroll
        for (int kt = 0; kt < 2; kt++) {
            int k0 = kt * 16 + 2 * tig;
            b2f[nt][kt][0] = f16pk(W2[e * 1024 + k0 * 32 + n],
                                   W2[e * 1024 + (k0 + 1) * 32 + n]);
            b2f[nt][kt][1] = f16pk(W2[e * 1024 + (k0 + 8) * 32 + n],
                                   W2[e * 1024 + (k0 + 9) * 32 + n]);
        }
        int c0 = nt * 8 + 2 * tig;
        bias1[nt][0] = b1[e * 32 + c0];
        bias1[nt][1] = b1[e * 32 + c0 + 1];
    }
    const float b3e0 = b3[e * 2], b3e1 = b3[e * 2 + 1];
    __syncthreads();

    for (int tile = blockIdx.x; tile < NTILES; tile += gridDim.x) {
        const int tok = tile * 256 + tid;

        // ================= phase 1: x load, gate, staging =================
        float x[10];
        {
            const float2* xp = reinterpret_cast<const float2*>(X + (size_t)tok * 10);
            #pragma unroll
            for (int i = 0; i < 5; i++) { float2 v = xp[i]; x[2*i] = v.x; x[2*i+1] = v.y; }
        }

        float wsum;
        {
            u64 l2a[4];
            const float2* gb2p = (const float2*)(sf + FGB2);
            #pragma unroll
            for (int j = 0; j < 4; j++) l2a[j] = f2u(gb2p[j]);
            #pragma unroll 1
            for (int c = 0; c < 4; c++) {
                u64 acc[8];
                const float2* bp = (const float2*)(sf + FGB1 + c * 16);
                #pragma unroll
                for (int j = 0; j < 8; j++) acc[j] = f2u(bp[j]);
                #pragma unroll
                for (int k = 0; k < 10; k++) {
                    u64 m = pkdup(x[k]);
                    const float4* wr = (const float4*)(sf + FG1 + k * 64 + c * 16);
                    #pragma unroll
                    for (int j = 0; j < 4; j++) {
                        float4 w = wr[j];
                        acc[2*j]   = fma2(m, pk(w.x, w.y), acc[2*j]);
                        acc[2*j+1] = fma2(m, pk(w.z, w.w), acc[2*j+1]);
                    }
                }
                #pragma unroll
                for (int j = 0; j < 8; j++) {
                    const float4* g2r = (const float4*)(sf + FG2 + (c * 16 + 2 * j) * 8);
                    float4 ra0 = g2r[0], ra1 = g2r[1], rb0 = g2r[2], rb1_ = g2r[3];
                    float p, q; upk(acc[j], p, q);
                    p = fmaxf(p, 0.f); q = fmaxf(q, 0.f);
                    u64 mp = pkdup(p), mq = pkdup(q);
                    l2a[0] = fma2(mp, pk(ra0.x, ra0.y), l2a[0]);
                    l2a[1] = fma2(mp, pk(ra0.z, ra0.w), l2a[1]);
                    l2a[2] = fma2(mp, pk(ra1.x, ra1.y), l2a[2]);
                    l2a[3] = fma2(mp, pk(ra1.z, ra1.w), l2a[3]);
                    l2a[0] = fma2(mq, pk(rb0.x, rb0.y), l2a[0]);
                    l2a[1] = fma2(mq, pk(rb0.z, rb0.w), l2a[1]);
                    l2a[2] = fma2(mq, pk(rb1_.x, rb1_.y), l2a[2]);
                    l2a[3] = fma2(mq, pk(rb1_.z, rb1_.w), l2a[3]);
                }
            }
            float l[8];
            #pragma unroll
            for (int j = 0; j < 4; j++) upk(l2a[j], l[2*j], l[2*j+1]);
            float m = l[0];
            #pragma unroll
            for (int i = 1; i < 8; i++) m = fmaxf(m, l[i]);
            wsum = 0.f;
            float* wxp = reinterpret_cast<float*>(smem_raw + WX);
            #pragma unroll
            for (int i = 0; i < 8; i++) {
                float v = __expf(l[i] - m); wsum += v;
                wxp[i * 256 + tid] = v;
            }
        }

        // stage x fp16 fragments: row = tid, 32B data (k0-15, zero-padded)
        {
            u32 xs[5];
            #pragma unroll
            for (int i = 0; i < 5; i++) xs[i] = f16pk(x[2*i], x[2*i+1]);
            uint4* p = reinterpret_cast<uint4*>(smem_raw + XB + tid * 48);
            p[0] = make_uint4(xs[0], xs[1], xs[2], xs[3]);
            p[1] = make_uint4(xs[4], 0u, 0u, 0u);
        }
        __syncthreads();

        // ================= phase 2: expert GEMMs (warp = expert) =================
        {
            const float* wxp = reinterpret_cast<const float*>(smem_raw + WX);
            float2* fup = reinterpret_cast<float2*>(smem_raw + FU);
            #pragma unroll 1
            for (int mt = 0; mt < 16; mt++) {
                // x A-fragments via single ldmatrix
                u32 ax[4];
                ldm_x4(ax, sbase + XB + (u32)(mt * 16 + (lane & 15)) * 48
                           + ((lane >> 4) << 4));

                // L1: 4 n-tiles, bias via C operand
                float d[4][4];
                #pragma unroll
                for (int nt = 0; nt < 4; nt++)
                    mma_f16_c(d[nt][0], d[nt][1], d[nt][2], d[nt][3],
                              ax[0], ax[1], ax[2], ax[3],
                              b1f[nt][0], b1f[nt][1], bias1[nt][0], bias1[nt][1]);

                // epilogue: relu, pack -> L2 A-fragments (registers only)
                u32 a2[2][4];
                #pragma unroll
                for (int nt = 0; nt < 4; nt++) {
                    float v0 = fmaxf(d[nt][0], 0.f);
                    float v1 = fmaxf(d[nt][1], 0.f);
                    float v2 = fmaxf(d[nt][2], 0.f);
                    float v3 = fmaxf(d[nt][3], 0.f);
                    int kt = nt >> 1, hf = (nt & 1) << 1;
                    a2[kt][hf]     = f16pk(v0, v1);
                    a2[kt][hf + 1] = f16pk(v2, v3);
                }

                // L2: 4 n-tiles x 2 k-chunks, bias via C on first
                float g[4][4];
                #pragma unroll
                for (int nt = 0; nt < 4; nt++) {
                    float2 tb = *reinterpret_cast<const float2*>(
                        smem_raw + TB2 + (u32)(((e * 4 + nt) * 4 + tig)) * 8);
                    mma_f16_c(g[nt][0], g[nt][1], g[nt][2], g[nt][3],
                              a2[0][0], a2[0][1], a2[0][2], a2[0][3],
                              b2f[nt][0][0], b2f[nt][0][1], tb.x, tb.y);
                    mma_f16_acc(g[nt][0], g[nt][1], g[nt][2], g[nt][3],
                                a2[1][0], a2[1][1], a2[1][2], a2[1][3],
                                b2f[nt][1][0], b2f[nt][1][1]);
                }

                // epilogue: relu + L3 fold (packed fma2)
                u64 oA = 0ull, oB = 0ull;
                #pragma unroll
                for (int nt = 0; nt < 4; nt++) {
                    float4 w3v = *reinterpret_cast<const float4*>(
                        smem_raw + TW3 + (u32)(((e * 4 + nt) * 4 + tig)) * 16);
                    u64 wA = pk(w3v.x, w3v.y), wB = pk(w3v.z, w3v.w);
                    float v0 = fmaxf(g[nt][0], 0.f);
                    float v1 = fmaxf(g[nt][1], 0.f);
                    float v2 = fmaxf(g[nt][2], 0.f);
                    float v3 = fmaxf(g[nt][3], 0.f);
                    oA = fma2(pkdup(v0), wA, oA);
                    oA = fma2(pkdup(v1), wB, oA);
                    oB = fma2(pkdup(v2), wA, oB);
                    oB = fma2(pkdup(v3), wB, oB);
                }
                float oA0, oA1, oB0, oB1;
                upk(oA, oA0, oA1); upk(oB, oB0, oB1);
                oA0 += __shfl_xor_sync(0xFFFFFFFFu, oA0, 1);
                oA0 += __shfl_xor_sync(0xFFFFFFFFu, oA0, 2);
                oA1 += __shfl_xor_sync(0xFFFFFFFFu, oA1, 1);
                oA1 += __shfl_xor_sync(0xFFFFFFFFu, oA1, 2);
                oB0 += __shfl_xor_sync(0xFFFFFFFFu, oB0, 1);
                oB0 += __shfl_xor_sync(0xFFFFFFFFu, oB0, 2);
                oB1 += __shfl_xor_sync(0xFFFFFFFFu, oB1, 1);
                oB1 += __shfl_xor_sync(0xFFFFFFFFu, oB1, 2);
                if (tig < 2) {
                    int tk = mt * 16 + grp + 8 * tig;
                    float u0 = tig ? oB0 : oA0;
                    float u1 = tig ? oB1 : oA1;
                    float s0 = tanh_acc(u0 + b3e0);
                    float s1 = tanh_acc(u1 + b3e1);
                    float wv = wxp[e * 256 + tk];
                    fup[e * 256 + tk] = make_float2(wv * s0, wv * s1);
                }
            }
        }
        __syncthreads();

        // ================= phase 3: refine (thread = token) =================
        float rin[12];
        {
            const float2* fup = reinterpret_cast<const float2*>(smem_raw + FU);
            float f0 = 0.f, f1 = 0.f;
            #pragma unroll
            for (int q = 0; q < 8; q++) {
                float2 v = fup[q * 256 + tid];
                f0 += v.x; f1 += v.y;
            }
            float inv = 1.0f / wsum;
            rin[0] = f0 * inv; rin[1] = f1 * inv;
            #pragma unroll
            for (int i = 0; i < 10; i++) rin[2 + i] = x[i];
        }
        u64 racc = f2u(*reinterpret_cast<const float2*>(sf + FRB2));
        #pragma unroll 1
        for (int c = 0; c < 4; c++) {
            u64 acc[8];
            const float2* bp = (const float2*)(sf + FRB1 + c * 16);
            #pragma unroll
            for (int j = 0; j < 8; j++) acc[j] = f2u(bp[j]);
            #pragma unroll
            for (int k = 0; k < 12; k++) {
                u64 m = pkdup(rin[k]);
                const float4* wr = (const float4*)(sf + FR1 + k * 64 + c * 16);
                #pragma unroll
                for (int j = 0; j < 4; j++) {
                    float4 w = wr[j];
                    acc[2*j]   = fma2(m, pk(w.x, w.y), acc[2*j]);
                    acc[2*j+1] = fma2(m, pk(w.z, w.w), acc[2*j+1]);
                }
            }
            #pragma unroll
            for (int j = 0; j < 8; j++) {
                const float2* r2 = (const float2*)(sf + FR2 + (c * 16 + 2 * j) * 2);
                u64 we = f2u(r2[0]), wo = f2u(r2[1]);
                float p, q; upk(acc[j], p, q);
                p = fmaxf(p, 0.f); q = fmaxf(q, 0.f);
                racc = fma2(pkdup(p), we, racc);
                racc = fma2(pkdup(q), wo, racc);
            }
        }
        {
            float y0, y1; upk(racc, y0, y1);
            reinterpret_cast<float2*>(out)[tok] =
                make_float2(tanh_acc(y0), tanh_acc(y1));
        }
    }
}

extern "C" void kernel_launch(void* const* d_in, const int* in_sizes, int n_in,
                              void* d_out, int out_size)
{
    (void)in_sizes; (void)n_in; (void)out_size;
    const float* X   = (const float*)d_in[0];
    const float* W1  = (const float*)d_in[1];
    const float* b1  = (const float*)d_in[2];
    const float* W2  = (const float*)d_in[3];
    const float* b2  = (const float*)d_in[4];
    const float* W3  = (const float*)d_in[5];
    const float* b3  = (const float*)d_in[6];
    const float* G1  = (const float*)d_in[7];
    const float* gb1 = (const float*)d_in[8];
    const float* G2  = (const float*)d_in[9];
    const float* gb2 = (const float*)d_in[10];
    const float* R1  = (const float*)d_in[11];
    const float* rb1 = (const float*)d_in[12];
    const float* R2  = (const float*)d_in[13];
    const float* rb2 = (const float*)d_in[14];

    cudaFuncSetAttribute(moe_r9_kernel,
                         cudaFuncAttributeMaxDynamicSharedMemorySize, SMEM_TOTAL);

    moe_r9_kernel<<<GRID, 256, SMEM_TOTAL>>>(
        X, W1, b1, W2, b2, W3, b3, G1, gb1, G2, gb2, R1, rb1, R2, rb2,
        (float*)d_out);
}

// round 10
// speedup vs baseline: 4.1489x; 1.5835x over previous
#include <cuda_runtime.h>
#include <cuda_fp16.h>
#include <cstdint>

// Round 10: EVERYTHING on tensor cores (fp16 mma, fp32 accum).
// Experts: warp-specialized, weights in registers (as R9).
// Gate + refine: mma with per-lane SMEM B-fragment tables; softmax via shfl.
// CTA = 256 threads = 8 warps, tile = 256 tokens, 3 syncthreads/tile.

#define NTILES 4096
#define GRID   592

typedef unsigned long long u64;
typedef unsigned int u32;

// ---------------- scalar fp32x2 helpers (expert L3 fold only) ----------------
__device__ __forceinline__ u64 pk(float a, float b) {
    u64 r; asm("mov.b64 %0,{%1,%2};" : "=l"(r) : "f"(a), "f"(b)); return r;
}
__device__ __forceinline__ u64 pkdup(float a) { return pk(a, a); }
__device__ __forceinline__ void upk(u64 v, float& a, float& b) {
    asm("mov.b64 {%0,%1},%2;" : "=f"(a), "=f"(b) : "l"(v));
}
__device__ __forceinline__ u64 fma2(u64 a, u64 b, u64 c) {
    u64 d; asm("fma.rn.f32x2 %0,%1,%2,%3;" : "=l"(d) : "l"(a), "l"(b), "l"(c)); return d;
}

// pack two floats to f16x2: low half = lo, high half = hi
__device__ __forceinline__ u32 f16pk(float lo, float hi) {
    u32 d; asm("cvt.rn.f16x2.f32 %0,%1,%2;" : "=r"(d) : "f"(hi), "f"(lo)); return d;
}
__device__ __forceinline__ float tanh_acc(float v) {
    float e = __expf(2.0f * v);
    return 1.0f - __fdividef(2.0f, e + 1.0f);
}

// ---------------- mma / ldmatrix ----------------
__device__ __forceinline__ void mma_f16_c(float& d0, float& d1, float& d2, float& d3,
                                          u32 a0, u32 a1, u32 a2, u32 a3,
                                          u32 b0, u32 b1, float c0, float c1) {
    asm volatile("mma.sync.aligned.m16n8k16.row.col.f32.f16.f16.f32 "
                 "{%0,%1,%2,%3},{%4,%5,%6,%7},{%8,%9},{%10,%11,%10,%11};"
                 : "=f"(d0), "=f"(d1), "=f"(d2), "=f"(d3)
                 : "r"(a0), "r"(a1), "r"(a2), "r"(a3), "r"(b0), "r"(b1),
                   "f"(c0), "f"(c1));
}
__device__ __forceinline__ void mma_f16_acc(float& d0, float& d1, float& d2, float& d3,
                                            u32 a0, u32 a1, u32 a2, u32 a3,
                                            u32 b0, u32 b1) {
    asm volatile("mma.sync.aligned.m16n8k16.row.col.f32.f16.f16.f32 "
                 "{%0,%1,%2,%3},{%4,%5,%6,%7},{%8,%9},{%0,%1,%2,%3};"
                 : "+f"(d0), "+f"(d1), "+f"(d2), "+f"(d3)
                 : "r"(a0), "r"(a1), "r"(a2), "r"(a3), "r"(b0), "r"(b1));
}
__device__ __forceinline__ void ldm_x4(u32* r, u32 addr) {
    asm volatile("ldmatrix.sync.aligned.m8n8.x4.shared.b16 {%0,%1,%2,%3}, [%4];"
                 : "=r"(r[0]), "=r"(r[1]), "=r"(r[2]), "=r"(r[3]) : "r"(addr));
}
__device__ __forceinline__ u32 smem_to_u32(const void* p) {
    u32 a;
    asm("{ .reg .u64 t; cvta.to.shared.u64 t, %1; cvt.u32.u64 %0, t; }" : "=r"(a) : "l"(p));
    return a;
}

// ---------------- SMEM layout (bytes) ----------------
#define XB  0        // x fp16 rows: 256 x 48B
#define RB  12288    // rin fp16 rows: 256 x 48B
#define WX  24576    // normalized gate weights [8][256] f32   (8 KB)
#define FU  32768    // expert outputs (unweighted) [8][256] float2 (16 KB)
#define TB2 49152    // expert bias2 table [e][nt][tig] float2  (1 KB)
#define TW3 50176    // expert w3 table    [e][nt][tig] float4  (2 KB)
#define GT  52224    // gate lane tables: 32 x 272B
#define RT  60928    // refine lane tables: 32 x 272B
#define SMEM_TOTAL 69632

extern __shared__ char smem_raw[];

__global__ void __launch_bounds__(256, 2)
moe_r10_kernel(const float* __restrict__ X,
               const float* __restrict__ W1, const float* __restrict__ b1,
               const float* __restrict__ W2, const float* __restrict__ b2,
               const float* __restrict__ W3, const float* __restrict__ b3,
               const float* __restrict__ G1, const float* __restrict__ gb1,
               const float* __restrict__ G2, const float* __restrict__ gb2,
               const float* __restrict__ R1, const float* __restrict__ rb1,
               const float* __restrict__ R2, const float* __restrict__ rb2,
               float* __restrict__ out)
{
    const int tid  = threadIdx.x;
    const int wid  = tid >> 5;     // = expert id
    const int lane = tid & 31;
    const int grp  = lane >> 2;
    const int tig  = lane & 3;
    const u32 sbase = smem_to_u32(smem_raw);

    // ---- expert bias2 / w3 broadcast tables ----
    if (tid < 128) {
        int te = tid >> 4, tn = (tid >> 2) & 3, tg = tid & 3;
        int c0 = tn * 8 + 2 * tg;
        *reinterpret_cast<float2*>(smem_raw + TB2 + tid * 8) =
            make_float2(b2[te * 32 + c0], b2[te * 32 + c0 + 1]);
        *reinterpret_cast<float4*>(smem_raw + TW3 + tid * 16) =
            make_float4(W3[(te * 32 + c0) * 2],     W3[(te * 32 + c0) * 2 + 1],
                        W3[(te * 32 + c0 + 1) * 2], W3[(te * 32 + c0 + 1) * 2 + 1]);
    }

    // ---- gate / refine per-lane fragment tables (272B stride, conflict-free) ----
    if (tid < 32) {
        int g = tid >> 2, t = tid & 3;
        int k0 = 2 * t;
        {
            char* gt = smem_raw + GT + tid * 272;
            u32*    b1t = reinterpret_cast<u32*>(gt);
            float2* c1t = reinterpret_cast<float2*>(gt + 64);
            u32*    b2t = reinterpret_cast<u32*>(gt + 128);
            float2* c2t = reinterpret_cast<float2*>(gt + 160);
            #pragma unroll
            for (int nt = 0; nt < 8; nt++) {
                int n = nt * 8 + g;
                b1t[nt * 2]     = f16pk(G1[k0 * 64 + n], G1[(k0 + 1) * 64 + n]);
                float wa = (k0 + 8 < 10) ? G1[(k0 + 8) * 64 + n] : 0.f;
                float wb = (k0 + 9 < 10) ? G1[(k0 + 9) * 64 + n] : 0.f;
                b1t[nt * 2 + 1] = f16pk(wa, wb);
                c1t[nt] = make_float2(gb1[nt * 8 + k0], gb1[nt * 8 + k0 + 1]);
            }
            #pragma unroll
            for (int kt = 0; kt < 4; kt++) {
                int kk = kt * 16 + k0;
                b2t[kt * 2]     = f16pk(G2[kk * 8 + g],       G2[(kk + 1) * 8 + g]);
                b2t[kt * 2 + 1] = f16pk(G2[(kk + 8) * 8 + g], G2[(kk + 9) * 8 + g]);
            }
            c2t[0] = make_float2(gb2[k0], gb2[k0 + 1]);
        }
        {
            char* rt = smem_raw + RT + tid * 272;
            u32*    b1t = reinterpret_cast<u32*>(rt);
            float2* c1t = reinterpret_cast<float2*>(rt + 64);
            u32*    b2t = reinterpret_cast<u32*>(rt + 128);
            float2* c2t = reinterpret_cast<float2*>(rt + 160);
            #pragma unroll
            for (int nt = 0; nt < 8; nt++) {
                int n = nt * 8 + g;
                b1t[nt * 2]     = f16pk(R1[k0 * 64 + n], R1[(k0 + 1) * 64 + n]);
                float wa = (k0 + 8 < 12) ? R1[(k0 + 8) * 64 + n] : 0.f;
                float wb = (k0 + 9 < 12) ? R1[(k0 + 9) * 64 + n] : 0.f;
                b1t[nt * 2 + 1] = f16pk(wa, wb);
                c1t[nt] = make_float2(rb1[nt * 8 + k0], rb1[nt * 8 + k0 + 1]);
            }
            #pragma unroll
            for (int kt = 0; kt < 4; kt++) {
                int kk = kt * 16 + k0;
                float wa0 = (g < 2) ? R2[kk * 2 + g] : 0.f;
                float wb0 = (g < 2) ? R2[(kk + 1) * 2 + g] : 0.f;
                b2t[kt * 2]     = f16pk(wa0, wb0);
                float wa1 = (g < 2) ? R2[(kk + 8) * 2 + g] : 0.f;
                float wb1 = (g < 2) ? R2[(kk + 9) * 2 + g] : 0.f;
                b2t[kt * 2 + 1] = f16pk(wa1, wb1);
            }
            c2t[0] = make_float2(t == 0 ? rb2[0] : 0.f, t == 0 ? rb2[1] : 0.f);
        }
    }

    // ---- register-resident fp16 expert fragments (warp e = expert e) ----
    const int e = wid;
    u32 b1f[4][2];            // [nt][b0/b1]
    u32 b2f[4][2][2];         // [nt][kt][b0/b1]
    float bias1[4][2];
    #pragma unroll
    for (int nt = 0; nt < 4; nt++) {
        int n = nt * 8 + grp;
        b1f[nt][0] = f16pk(W1[e * 320 + (2 * tig) * 32 + n],
                           W1[e * 320 + (2 * tig + 1) * 32 + n]);
        {
            float wa = (2 * tig + 8 < 10) ? W1[e * 320 + (2 * tig + 8) * 32 + n] : 0.f;
            float wb = (2 * tig + 9 < 10) ? W1[e * 320 + (2 * tig + 9) * 32 + n] : 0.f;
            b1f[nt][1] = f16pk(wa, wb);
        }
        #pragma unroll
        for (int kt = 0; kt < 2; kt++) {
            int k0 = kt * 16 + 2 * tig;
            b2f[nt][kt][0] = f16pk(W2[e * 1024 + k0 * 32 + n],
                                   W2[e * 1024 + (k0 + 1) * 32 + n]);
            b2f[nt][kt][1] = f16pk(W2[e * 1024 + (k0 + 8) * 32 + n],
                                   W2[e * 1024 + (k0 + 9) * 32 + n]);
        }
        int c0 = nt * 8 + 2 * tig;
        bias1[nt][0] = b1[e * 32 + c0];
        bias1[nt][1] = b1[e * 32 + c0 + 1];
    }
    const float b3e0 = b3[e * 2], b3e1 = b3[e * 2 + 1];
    __syncthreads();

    for (int tile = blockIdx.x; tile < NTILES; tile += gridDim.x) {
        const int tok = tile * 256 + tid;

        // ============ phase 1: load x, stage fp16 rows ============
        float x[10];
        u32 xs[5];
        {
            const float2* xp = reinterpret_cast<const float2*>(X + (size_t)tok * 10);
            #pragma unroll
            for (int i = 0; i < 5; i++) {
                float2 v = xp[i]; x[2*i] = v.x; x[2*i+1] = v.y;
                xs[i] = f16pk(v.x, v.y);
            }
            uint4* p = reinterpret_cast<uint4*>(smem_raw + XB + tid * 48);
            p[0] = make_uint4(xs[0], xs[1], xs[2], xs[3]);
            p[1] = make_uint4(xs[4], 0u, 0u, 0u);
        }
        __syncthreads();

        // ============ phase 2a: gate via mma (2 m-tiles per warp) ============
        {
            const char* gt = smem_raw + GT + (u32)lane * 272;
            const u32*    b1t = reinterpret_cast<const u32*>(gt);
            const float2* c1t = reinterpret_cast<const float2*>(gt + 64);
            const u32*    b2t = reinterpret_cast<const u32*>(gt + 128);
            const float2  c2  = *reinterpret_cast<const float2*>(gt + 160);
            float* wxp = reinterpret_cast<float*>(smem_raw + WX);
            #pragma unroll 1
            for (int q = 0; q < 2; q++) {
                int mt = wid * 2 + q;
                u32 ax[4];
                ldm_x4(ax, sbase + XB + (u32)(mt * 16 + (lane & 15)) * 48
                           + ((lane >> 4) << 4));
                float d[8][4];
                #pragma unroll
                for (int nt = 0; nt < 8; nt++) {
                    float2 cc = c1t[nt];
                    mma_f16_c(d[nt][0], d[nt][1], d[nt][2], d[nt][3],
                              ax[0], ax[1], ax[2], ax[3],
                              b1t[2*nt], b1t[2*nt+1], cc.x, cc.y);
                }
                u32 a2[4][4];
                #pragma unroll
                for (int kt = 0; kt < 4; kt++) {
                    a2[kt][0] = f16pk(fmaxf(d[2*kt][0],0.f),   fmaxf(d[2*kt][1],0.f));
                    a2[kt][1] = f16pk(fmaxf(d[2*kt][2],0.f),   fmaxf(d[2*kt][3],0.f));
                    a2[kt][2] = f16pk(fmaxf(d[2*kt+1][0],0.f), fmaxf(d[2*kt+1][1],0.f));
                    a2[kt][3] = f16pk(fmaxf(d[2*kt+1][2],0.f), fmaxf(d[2*kt+1][3],0.f));
                }
                float l0, l1, l2, l3;
                mma_f16_c(l0, l1, l2, l3,
                          a2[0][0], a2[0][1], a2[0][2], a2[0][3],
                          b2t[0], b2t[1], c2.x, c2.y);
                #pragma unroll
                for (int kt = 1; kt < 4; kt++)
                    mma_f16_acc(l0, l1, l2, l3,
                                a2[kt][0], a2[kt][1], a2[kt][2], a2[kt][3],
                                b2t[2*kt], b2t[2*kt+1]);
                // softmax per row (8 logits spread over quad, 2 per lane)
                float mA = fmaxf(l0, l1);
                mA = fmaxf(mA, __shfl_xor_sync(0xFFFFFFFFu, mA, 1));
                mA = fmaxf(mA, __shfl_xor_sync(0xFFFFFFFFu, mA, 2));
                float eA0 = __expf(l0 - mA), eA1 = __expf(l1 - mA);
                float sA = eA0 + eA1;
                sA += __shfl_xor_sync(0xFFFFFFFFu, sA, 1);
                sA += __shfl_xor_sync(0xFFFFFFFFu, sA, 2);
                float iA = __fdividef(1.f, sA);
                float mB = fmaxf(l2, l3);
                mB = fmaxf(mB, __shfl_xor_sync(0xFFFFFFFFu, mB, 1));
                mB = fmaxf(mB, __shfl_xor_sync(0xFFFFFFFFu, mB, 2));
                float eB0 = __expf(l2 - mB), eB1 = __expf(l3 - mB);
                float sB = eB0 + eB1;
                sB += __shfl_xor_sync(0xFFFFFFFFu, sB, 1);
                sB += __shfl_xor_sync(0xFFFFFFFFu, sB, 2);
                float iB = __fdividef(1.f, sB);
                int rowA = mt * 16 + grp;
                wxp[(2*tig)   * 256 + rowA]     = eA0 * iA;
                wxp[(2*tig+1) * 256 + rowA]     = eA1 * iA;
                wxp[(2*tig)   * 256 + rowA + 8] = eB0 * iB;
                wxp[(2*tig+1) * 256 + rowA + 8] = eB1 * iB;
            }
        }

        // ============ phase 2b: expert GEMMs (warp = expert, 16 m-tiles) ============
        {
            float2* fup = reinterpret_cast<float2*>(smem_raw + FU);
            #pragma unroll 1
            for (int mt = 0; mt < 16; mt++) {
                u32 ax[4];
                ldm_x4(ax, sbase + XB + (u32)(mt * 16 + (lane & 15)) * 48
                           + ((lane >> 4) << 4));
                float d[4][4];
                #pragma unroll
                for (int nt = 0; nt < 4; nt++)
                    mma_f16_c(d[nt][0], d[nt][1], d[nt][2], d[nt][3],
                              ax[0], ax[1], ax[2], ax[3],
                              b1f[nt][0], b1f[nt][1], bias1[nt][0], bias1[nt][1]);
                u32 a2[2][4];
                #pragma unroll
                for (int nt = 0; nt < 4; nt++) {
                    float v0 = fmaxf(d[nt][0], 0.f);
                    float v1 = fmaxf(d[nt][1], 0.f);
                    float v2 = fmaxf(d[nt][2], 0.f);
                    float v3 = fmaxf(d[nt][3], 0.f);
                    int kt = nt >> 1, hf = (nt & 1) << 1;
                    a2[kt][hf]     = f16pk(v0, v1);
                    a2[kt][hf + 1] = f16pk(v2, v3);
                }
                float g[4][4];
                #pragma unroll
                for (int nt = 0; nt < 4; nt++) {
                    float2 tb = *reinterpret_cast<const float2*>(
                        smem_raw + TB2 + (u32)(((e * 4 + nt) * 4 + tig)) * 8);
                    mma_f16_c(g[nt][0], g[nt][1], g[nt][2], g[nt][3],
                              a2[0][0], a2[0][1], a2[0][2], a2[0][3],
                              b2f[nt][0][0], b2f[nt][0][1], tb.x, tb.y);
                    mma_f16_acc(g[nt][0], g[nt][1], g[nt][2], g[nt][3],
                                a2[1][0], a2[1][1], a2[1][2], a2[1][3],
                                b2f[nt][1][0], b2f[nt][1][1]);
                }
                u64 oA = 0ull, oB = 0ull;
                #pragma unroll
                for (int nt = 0; nt < 4; nt++) {
                    float4 w3v = *reinterpret_cast<const float4*>(
                        smem_raw + TW3 + (u32)(((e * 4 + nt) * 4 + tig)) * 16);
                    u64 wA = pk(w3v.x, w3v.y), wB = pk(w3v.z, w3v.w);
                    float v0 = fmaxf(g[nt][0], 0.f);
                    float v1 = fmaxf(g[nt][1], 0.f);
                    float v2 = fmaxf(g[nt][2], 0.f);
                    float v3 = fmaxf(g[nt][3], 0.f);
                    oA = fma2(pkdup(v0), wA, oA);
                    oA = fma2(pkdup(v1), wB, oA);
                    oB = fma2(pkdup(v2), wA, oB);
                    oB = fma2(pkdup(v3), wB, oB);
                }
                float oA0, oA1, oB0, oB1;
                upk(oA, oA0, oA1); upk(oB, oB0, oB1);
                oA0 += __shfl_xor_sync(0xFFFFFFFFu, oA0, 1);
                oA0 += __shfl_xor_sync(0xFFFFFFFFu, oA0, 2);
                oA1 += __shfl_xor_sync(0xFFFFFFFFu, oA1, 1);
                oA1 += __shfl_xor_sync(0xFFFFFFFFu, oA1, 2);
                oB0 += __shfl_xor_sync(0xFFFFFFFFu, oB0, 1);
                oB0 += __shfl_xor_sync(0xFFFFFFFFu, oB0, 2);
                oB1 += __shfl_xor_sync(0xFFFFFFFFu, oB1, 1);
                oB1 += __shfl_xor_sync(0xFFFFFFFFu, oB1, 2);
                if (tig < 2) {
                    int tk = mt * 16 + grp + 8 * tig;
                    float u0 = tig ? oB0 : oA0;
                    float u1 = tig ? oB1 : oA1;
                    fup[e * 256 + tk] =
                        make_float2(tanh_acc(u0 + b3e0), tanh_acc(u1 + b3e1));
                }
            }
        }
        __syncthreads();

        // ============ phase 3: fuse + restage rin ============
        {
            const float2* fup = reinterpret_cast<const float2*>(smem_raw + FU);
            const float* wxp = reinterpret_cast<const float*>(smem_raw + WX);
            float f0 = 0.f, f1 = 0.f;
            #pragma unroll
            for (int q2 = 0; q2 < 8; q2++) {
                float2 s = fup[q2 * 256 + tid];
                float w = wxp[q2 * 256 + tid];
                f0 += w * s.x; f1 += w * s.y;
            }
            uint4* p = reinterpret_cast<uint4*>(smem_raw + RB + tid * 48);
            p[0] = make_uint4(f16pk(f0, f1), xs[0], xs[1], xs[2]);
            p[1] = make_uint4(xs[3], xs[4], 0u, 0u);
        }
        __syncthreads();

        // ============ phase 4: refine via mma (2 m-tiles per warp) ============
        {
            const char* rt = smem_raw + RT + (u32)lane * 272;
            const u32*    b1t = reinterpret_cast<const u32*>(rt);
            const float2* c1t = reinterpret_cast<const float2*>(rt + 64);
            const u32*    b2t = reinterpret_cast<const u32*>(rt + 128);
            const float2  c2  = *reinterpret_cast<const float2*>(rt + 160);
            float2* out2 = reinterpret_cast<float2*>(out);
            #pragma unroll 1
            for (int q = 0; q < 2; q++) {
                int mt = wid * 2 + q;
                u32 ax[4];
                ldm_x4(ax, sbase + RB + (u32)(mt * 16 + (lane & 15)) * 48
                           + ((lane >> 4) << 4));
                float d[8][4];
                #pragma unroll
                for (int nt = 0; nt < 8; nt++) {
                    float2 cc = c1t[nt];
                    mma_f16_c(d[nt][0], d[nt][1], d[nt][2], d[nt][3],
                              ax[0], ax[1], ax[2], ax[3],
                              b1t[2*nt], b1t[2*nt+1], cc.x, cc.y);
                }
                u32 a2[4][4];
                #pragma unroll
                for (int kt = 0; kt < 4; kt++) {
                    a2[kt][0] = f16pk(fmaxf(d[2*kt][0],0.f),   fmaxf(d[2*kt][1],0.f));
                    a2[kt][1] = f16pk(fmaxf(d[2*kt][2],0.f),   fmaxf(d[2*kt][3],0.f));
                    a2[kt][2] = f16pk(fmaxf(d[2*kt+1][0],0.f), fmaxf(d[2*kt+1][1],0.f));
                    a2[kt][3] = f16pk(fmaxf(d[2*kt+1][2],0.f), fmaxf(d[2*kt+1][3],0.f));
                }
                float y0, y1, y2, y3;
                mma_f16_c(y0, y1, y2, y3,
                          a2[0][0], a2[0][1], a2[0][2], a2[0][3],
                          b2t[0], b2t[1], c2.x, c2.y);
                #pragma unroll
                for (int kt = 1; kt < 4; kt++)
                    mma_f16_acc(y0, y1, y2, y3,
                                a2[kt][0], a2[kt][1], a2[kt][2], a2[kt][3],
                                b2t[2*kt], b2t[2*kt+1]);
                if (tig == 0) {
                    int rowA = tile * 256 + mt * 16 + grp;
                    out2[rowA]     = make_float2(tanh_acc(y0), tanh_acc(y1));
                    out2[rowA + 8] = make_float2(tanh_acc(y2), tanh_acc(y3));
                }
            }
        }
    }
}

extern "C" void kernel_launch(void* const* d_in, const int* in_sizes, int n_in,
                              void* d_out, int out_size)
{
    (void)in_sizes; (void)n_in; (void)out_size;
    const float* X   = (const float*)d_in[0];
    const float* W1  = (const float*)d_in[1];
    const float* b1  = (const float*)d_in[2];
    const float* W2  = (const float*)d_in[3];
    const float* b2  = (const float*)d_in[4];
    const float* W3  = (const float*)d_in[5];
    const float* b3  = (const float*)d_in[6];
    const float* G1  = (const float*)d_in[7];
    const float* gb1 = (const float*)d_in[8];
    const float* G2  = (const float*)d_in[9];
    const float* gb2 = (const float*)d_in[10];
    const float* R1  = (const float*)d_in[11];
    const float* rb1 = (const float*)d_in[12];
    const float* R2  = (const float*)d_in[13];
    const float* rb2 = (const float*)d_in[14];

    cudaFuncSetAttribute(moe_r10_kernel,
                         cudaFuncAttributeMaxDynamicSharedMemorySize, SMEM_TOTAL);

    moe_r10_kernel<<<GRID, 256, SMEM_TOTAL>>>(
        X, W1, b1, W2, b2, W3, b3, G1, gb1, G2, gb2, R1, rb1, R2, rb2,
        (float*)d_out);
}

// round 11
// speedup vs baseline: 4.5070x; 1.0863x over previous
#include <cuda_runtime.h>
#include <cuda_fp16.h>
#include <cstdint>

// Round 11: everything fp16 mma; expert L3 (32->2) is an mma pair too (zero
// shfl in mainloop); packed-relu epilogues (max.f16x2). Expert weights in regs.
// CTA = 256 threads = 8 warps (warp e = expert e), tile = 256 tokens.

#define NTILES 4096
#define GRID   592

typedef unsigned int u32;

// pack two floats to f16x2: low half = lo, high half = hi
__device__ __forceinline__ u32 f16pk(float lo, float hi) {
    u32 d; asm("cvt.rn.f16x2.f32 %0,%1,%2;" : "=r"(d) : "f"(hi), "f"(lo)); return d;
}
// packed relu: round pair to fp16, then max with +0
__device__ __forceinline__ u32 relu_pk(float lo, float hi) {
    u32 d = f16pk(lo, hi);
    u32 r; asm("max.f16x2 %0,%1,%2;" : "=r"(r) : "r"(d), "r"(0u)); return r;
}
__device__ __forceinline__ float tanh_acc(float v) {
    float e = __expf(2.0f * v);
    return 1.0f - __fdividef(2.0f, e + 1.0f);
}

// ---------------- mma / ldmatrix ----------------
__device__ __forceinline__ void mma_f16_c(float& d0, float& d1, float& d2, float& d3,
                                          u32 a0, u32 a1, u32 a2, u32 a3,
                                          u32 b0, u32 b1, float c0, float c1) {
    asm volatile("mma.sync.aligned.m16n8k16.row.col.f32.f16.f16.f32 "
                 "{%0,%1,%2,%3},{%4,%5,%6,%7},{%8,%9},{%10,%11,%10,%11};"
                 : "=f"(d0), "=f"(d1), "=f"(d2), "=f"(d3)
                 : "r"(a0), "r"(a1), "r"(a2), "r"(a3), "r"(b0), "r"(b1),
                   "f"(c0), "f"(c1));
}
__device__ __forceinline__ void mma_f16_acc(float& d0, float& d1, float& d2, float& d3,
                                            u32 a0, u32 a1, u32 a2, u32 a3,
                                            u32 b0, u32 b1) {
    asm volatile("mma.sync.aligned.m16n8k16.row.col.f32.f16.f16.f32 "
                 "{%0,%1,%2,%3},{%4,%5,%6,%7},{%8,%9},{%0,%1,%2,%3};"
                 : "+f"(d0), "+f"(d1), "+f"(d2), "+f"(d3)
                 : "r"(a0), "r"(a1), "r"(a2), "r"(a3), "r"(b0), "r"(b1));
}
__device__ __forceinline__ void ldm_x4(u32* r, u32 addr) {
    asm volatile("ldmatrix.sync.aligned.m8n8.x4.shared.b16 {%0,%1,%2,%3}, [%4];"
                 : "=r"(r[0]), "=r"(r[1]), "=r"(r[2]), "=r"(r[3]) : "r"(addr));
}
__device__ __forceinline__ u32 smem_to_u32(const void* p) {
    u32 a;
    asm("{ .reg .u64 t; cvta.to.shared.u64 t, %1; cvt.u32.u64 %0, t; }" : "=r"(a) : "l"(p));
    return a;
}

// ---------------- SMEM layout (bytes) ----------------
#define XB  0        // x fp16 rows: 256 x 48B
#define RB  12288    // rin fp16 rows: 256 x 48B
#define WX  24576    // normalized gate weights [8][256] f32   (8 KB)
#define FU  32768    // expert outputs (unweighted tanh) [8][256] float2 (16 KB)
#define TB2 49152    // expert bias2 table [e][nt][tig] float2  (1 KB)
#define GT  50176    // gate lane tables: 32 x 272B
#define RT  58880    // refine lane tables: 32 x 272B
#define SMEM_TOTAL 67584

extern __shared__ char smem_raw[];

__global__ void __launch_bounds__(256, 2)
moe_r11_kernel(const float* __restrict__ X,
               const float* __restrict__ W1, const float* __restrict__ b1,
               const float* __restrict__ W2, const float* __restrict__ b2,
               const float* __restrict__ W3, const float* __restrict__ b3,
               const float* __restrict__ G1, const float* __restrict__ gb1,
               const float* __restrict__ G2, const float* __restrict__ gb2,
               const float* __restrict__ R1, const float* __restrict__ rb1,
               const float* __restrict__ R2, const float* __restrict__ rb2,
               float* __restrict__ out)
{
    const int tid  = threadIdx.x;
    const int wid  = tid >> 5;     // = expert id
    const int lane = tid & 31;
    const int grp  = lane >> 2;
    const int tig  = lane & 3;
    const u32 sbase = smem_to_u32(smem_raw);

    // ---- expert bias2 broadcast table ----
    if (tid < 128) {
        int te = tid >> 4, tn = (tid >> 2) & 3, tg = tid & 3;
        int c0 = tn * 8 + 2 * tg;
        *reinterpret_cast<float2*>(smem_raw + TB2 + tid * 8) =
            make_float2(b2[te * 32 + c0], b2[te * 32 + c0 + 1]);
    }

    // ---- gate / refine per-lane fragment tables (272B stride, conflict-free) ----
    if (tid < 32) {
        int g = tid >> 2, t = tid & 3;
        int k0 = 2 * t;
        {
            char* gt = smem_raw + GT + tid * 272;
            u32*    b1t = reinterpret_cast<u32*>(gt);
            float2* c1t = reinterpret_cast<float2*>(gt + 64);
            u32*    b2t = reinterpret_cast<u32*>(gt + 128);
            float2* c2t = reinterpret_cast<float2*>(gt + 160);
            #pragma unroll
            for (int nt = 0; nt < 8; nt++) {
                int n = nt * 8 + g;
                b1t[nt * 2]     = f16pk(G1[k0 * 64 + n], G1[(k0 + 1) * 64 + n]);
                float wa = (k0 + 8 < 10) ? G1[(k0 + 8) * 64 + n] : 0.f;
                float wb = (k0 + 9 < 10) ? G1[(k0 + 9) * 64 + n] : 0.f;
                b1t[nt * 2 + 1] = f16pk(wa, wb);
                c1t[nt] = make_float2(gb1[nt * 8 + k0], gb1[nt * 8 + k0 + 1]);
            }
            #pragma unroll
            for (int kt = 0; kt < 4; kt++) {
                int kk = kt * 16 + k0;
                b2t[kt * 2]     = f16pk(G2[kk * 8 + g],       G2[(kk + 1) * 8 + g]);
                b2t[kt * 2 + 1] = f16pk(G2[(kk + 8) * 8 + g], G2[(kk + 9) * 8 + g]);
            }
            c2t[0] = make_float2(gb2[k0], gb2[k0 + 1]);
        }
        {
            char* rt = smem_raw + RT + tid * 272;
            u32*    b1t = reinterpret_cast<u32*>(rt);
            float2* c1t = reinterpret_cast<float2*>(rt + 64);
            u32*    b2t = reinterpret_cast<u32*>(rt + 128);
            float2* c2t = reinterpret_cast<float2*>(rt + 160);
            #pragma unroll
            for (int nt = 0; nt < 8; nt++) {
                int n = nt * 8 + g;
                b1t[nt * 2]     = f16pk(R1[k0 * 64 + n], R1[(k0 + 1) * 64 + n]);
                float wa = (k0 + 8 < 12) ? R1[(k0 + 8) * 64 + n] : 0.f;
                float wb = (k0 + 9 < 12) ? R1[(k0 + 9) * 64 + n] : 0.f;
                b1t[nt * 2 + 1] = f16pk(wa, wb);
                c1t[nt] = make_float2(rb1[nt * 8 + k0], rb1[nt * 8 + k0 + 1]);
            }
            #pragma unroll
            for (int kt = 0; kt < 4; kt++) {
                int kk = kt * 16 + k0;
                float wa0 = (g < 2) ? R2[kk * 2 + g] : 0.f;
                float wb0 = (g < 2) ? R2[(kk + 1) * 2 + g] : 0.f;
                b2t[kt * 2]     = f16pk(wa0, wb0);
                float wa1 = (g < 2) ? R2[(kk + 8) * 2 + g] : 0.f;
                float wb1 = (g < 2) ? R2[(kk + 9) * 2 + g] : 0.f;
                b2t[kt * 2 + 1] = f16pk(wa1, wb1);
            }
            c2t[0] = make_float2(t == 0 ? rb2[0] : 0.f, t == 0 ? rb2[1] : 0.f);
        }
    }

    // ---- register-resident fp16 expert fragments (warp e = expert e) ----
    const int e = wid;
    u32 b1f[4][2];            // W1 [nt][b0/b1]
    u32 b2f[4][2][2];         // W2 [nt][kt][b0/b1]
    u32 w3f[2][2];            // W3 [kc][b0/b1], n = grp (zero for grp >= 2)
    float bias1[4][2];
    #pragma unroll
    for (int nt = 0; nt < 4; nt++) {
        int n = nt * 8 + grp;
        b1f[nt][0] = f16pk(W1[e * 320 + (2 * tig) * 32 + n],
                           W1[e * 320 + (2 * tig + 1) * 32 + n]);
        {
            float wa = (2 * tig + 8 < 10) ? W1[e * 320 + (2 * tig + 8) * 32 + n] : 0.f;
            float wb = (2 * tig + 9 < 10) ? W1[e * 320 + (2 * tig + 9) * 32 + n] : 0.f;
            b1f[nt][1] = f16pk(wa, wb);
        }
        #pragma unroll
        for (int kt = 0; kt < 2; kt++) {
            int k0 = kt * 16 + 2 * tig;
            b2f[nt][kt][0] = f16pk(W2[e * 1024 + k0 * 32 + n],
                                   W2[e * 1024 + (k0 + 1) * 32 + n]);
            b2f[nt][kt][1] = f16pk(W2[e * 1024 + (k0 + 8) * 32 + n],
                                   W2[e * 1024 + (k0 + 9) * 32 + n]);
        }
        int c0 = nt * 8 + 2 * tig;
        bias1[nt][0] = b1[e * 32 + c0];
        bias1[nt][1] = b1[e * 32 + c0 + 1];
    }
    #pragma unroll
    for (int kc = 0; kc < 2; kc++) {
        int kb = kc * 16;
        float v00 = (grp < 2) ? W3[e * 64 + (kb + 2 * tig) * 2 + grp] : 0.f;
        float v01 = (grp < 2) ? W3[e * 64 + (kb + 2 * tig + 1) * 2 + grp] : 0.f;
        w3f[kc][0] = f16pk(v00, v01);
        float v10 = (grp < 2) ? W3[e * 64 + (kb + 8 + 2 * tig) * 2 + grp] : 0.f;
        float v11 = (grp < 2) ? W3[e * 64 + (kb + 9 + 2 * tig) * 2 + grp] : 0.f;
        w3f[kc][1] = f16pk(v10, v11);
    }
    const float b3e0 = b3[e * 2], b3e1 = b3[e * 2 + 1];
    __syncthreads();

    for (int tile = blockIdx.x; tile < NTILES; tile += gridDim.x) {
        const int tok = tile * 256 + tid;

        // ============ phase 1: load x, stage fp16 rows ============
        u32 xs[5];
        {
            const float2* xp = reinterpret_cast<const float2*>(X + (size_t)tok * 10);
            #pragma unroll
            for (int i = 0; i < 5; i++) {
                float2 v = xp[i];
                xs[i] = f16pk(v.x, v.y);
            }
            uint4* p = reinterpret_cast<uint4*>(smem_raw + XB + tid * 48);
            p[0] = make_uint4(xs[0], xs[1], xs[2], xs[3]);
            p[1] = make_uint4(xs[4], 0u, 0u, 0u);
        }
        __syncthreads();

        // ============ phase 2a: gate via mma (2 m-tiles per warp) ============
        {
            const char* gt = smem_raw + GT + (u32)lane * 272;
            const u32*    b1t = reinterpret_cast<const u32*>(gt);
            const float2* c1t = reinterpret_cast<const float2*>(gt + 64);
            const u32*    b2t = reinterpret_cast<const u32*>(gt + 128);
            const float2  c2  = *reinterpret_cast<const float2*>(gt + 160);
            float* wxp = reinterpret_cast<float*>(smem_raw + WX);
            #pragma unroll 1
            for (int q = 0; q < 2; q++) {
                int mt = wid * 2 + q;
                u32 ax[4];
                ldm_x4(ax, sbase + XB + (u32)(mt * 16 + (lane & 15)) * 48
                           + ((lane >> 4) << 4));
                float d[8][4];
                #pragma unroll
                for (int nt = 0; nt < 8; nt++) {
                    float2 cc = c1t[nt];
                    mma_f16_c(d[nt][0], d[nt][1], d[nt][2], d[nt][3],
                              ax[0], ax[1], ax[2], ax[3],
                              b1t[2*nt], b1t[2*nt+1], cc.x, cc.y);
                }
                u32 a2[4][4];
                #pragma unroll
                for (int kt = 0; kt < 4; kt++) {
                    a2[kt][0] = relu_pk(d[2*kt][0],   d[2*kt][1]);
                    a2[kt][1] = relu_pk(d[2*kt][2],   d[2*kt][3]);
                    a2[kt][2] = relu_pk(d[2*kt+1][0], d[2*kt+1][1]);
                    a2[kt][3] = relu_pk(d[2*kt+1][2], d[2*kt+1][3]);
                }
                float l0, l1, l2, l3;
                mma_f16_c(l0, l1, l2, l3,
                          a2[0][0], a2[0][1], a2[0][2], a2[0][3],
                          b2t[0], b2t[1], c2.x, c2.y);
                #pragma unroll
                for (int kt = 1; kt < 4; kt++)
                    mma_f16_acc(l0, l1, l2, l3,
                                a2[kt][0], a2[kt][1], a2[kt][2], a2[kt][3],
                                b2t[2*kt], b2t[2*kt+1]);
                // softmax per row (8 logits spread over quad, 2 per lane)
                float mA = fmaxf(l0, l1);
                mA = fmaxf(mA, __shfl_xor_sync(0xFFFFFFFFu, mA, 1));
                mA = fmaxf(mA, __shfl_xor_sync(0xFFFFFFFFu, mA, 2));
                float eA0 = __expf(l0 - mA), eA1 = __expf(l1 - mA);
                float sA = eA0 + eA1;
                sA += __shfl_xor_sync(0xFFFFFFFFu, sA, 1);
                sA += __shfl_xor_sync(0xFFFFFFFFu, sA, 2);
                float iA = __fdividef(1.f, sA);
                float mB = fmaxf(l2, l3);
                mB = fmaxf(mB, __shfl_xor_sync(0xFFFFFFFFu, mB, 1));
                mB = fmaxf(mB, __shfl_xor_sync(0xFFFFFFFFu, mB, 2));
                float eB0 = __expf(l2 - mB), eB1 = __expf(l3 - mB);
                float sB = eB0 + eB1;
                sB += __shfl_xor_sync(0xFFFFFFFFu, sB, 1);
                sB += __shfl_xor_sync(0xFFFFFFFFu, sB, 2);
                float iB = __fdividef(1.f, sB);
                int rowA = mt * 16 + grp;
                wxp[(2*tig)   * 256 + rowA]     = eA0 * iA;
                wxp[(2*tig+1) * 256 + rowA]     = eA1 * iA;
                wxp[(2*tig)   * 256 + rowA + 8] = eB0 * iB;
                wxp[(2*tig+1) * 256 + rowA + 8] = eB1 * iB;
            }
        }

        // ============ phase 2b: expert GEMMs (warp = expert, 16 m-tiles) ============
        {
            float2* fup = reinterpret_cast<float2*>(smem_raw + FU);
            #pragma unroll 1
            for (int mt = 0; mt < 16; mt++) {
                u32 ax[4];
                ldm_x4(ax, sbase + XB + (u32)(mt * 16 + (lane & 15)) * 48
                           + ((lane >> 4) << 4));
                // L1 (bias in C)
                float d[4][4];
                #pragma unroll
                for (int nt = 0; nt < 4; nt++)
                    mma_f16_c(d[nt][0], d[nt][1], d[nt][2], d[nt][3],
                              ax[0], ax[1], ax[2], ax[3],
                              b1f[nt][0], b1f[nt][1], bias1[nt][0], bias1[nt][1]);
                // packed relu -> L2 A-frags
                u32 a2[2][4];
                #pragma unroll
                for (int nt = 0; nt < 4; nt++) {
                    int kt = nt >> 1, hf = (nt & 1) << 1;
                    a2[kt][hf]     = relu_pk(d[nt][0], d[nt][1]);
                    a2[kt][hf + 1] = relu_pk(d[nt][2], d[nt][3]);
                }
                // L2 (bias2 from table via C)
                float g[4][4];
                #pragma unroll
                for (int nt = 0; nt < 4; nt++) {
                    float2 tb = *reinterpret_cast<const float2*>(
                        smem_raw + TB2 + (u32)(((e * 4 + nt) * 4 + tig)) * 8);
                    mma_f16_c(g[nt][0], g[nt][1], g[nt][2], g[nt][3],
                              a2[0][0], a2[0][1], a2[0][2], a2[0][3],
                              b2f[nt][0][0], b2f[nt][0][1], tb.x, tb.y);
                    mma_f16_acc(g[nt][0], g[nt][1], g[nt][2], g[nt][3],
                                a2[1][0], a2[1][1], a2[1][2], a2[1][3],
                                b2f[nt][1][0], b2f[nt][1][1]);
                }
                // packed relu -> L3 A-frags
                u32 p3[4][2];
                #pragma unroll
                for (int nt = 0; nt < 4; nt++) {
                    p3[nt][0] = relu_pk(g[nt][0], g[nt][1]);
                    p3[nt][1] = relu_pk(g[nt][2], g[nt][3]);
                }
                // L3 via mma pair (bias3 in C); valid cols 0,1 land on tig==0
                float y0, y1, y2, y3;
                mma_f16_c(y0, y1, y2, y3,
                          p3[0][0], p3[0][1], p3[1][0], p3[1][1],
                          w3f[0][0], w3f[0][1], b3e0, b3e1);
                mma_f16_acc(y0, y1, y2, y3,
                            p3[2][0], p3[2][1], p3[3][0], p3[3][1],
                            w3f[1][0], w3f[1][1]);
                if (tig == 0) {
                    int tk = mt * 16 + grp;
                    fup[e * 256 + tk]     = make_float2(tanh_acc(y0), tanh_acc(y1));
                    fup[e * 256 + tk + 8] = make_float2(tanh_acc(y2), tanh_acc(y3));
                }
            }
        }
        __syncthreads();

        // ============ phase 3: fuse + restage rin ============
        {
            const float2* fup = reinterpret_cast<const float2*>(smem_raw + FU);
            const float* wxp = reinterpret_cast<const float*>(smem_raw + WX);
            float f0 = 0.f, f1 = 0.f;
            #pragma unroll
            for (int q2 = 0; q2 < 8; q2++) {
                float2 s = fup[q2 * 256 + tid];
                float w = wxp[q2 * 256 + tid];
                f0 += w * s.x; f1 += w * s.y;
            }
            uint4* p = reinterpret_cast<uint4*>(smem_raw + RB + tid * 48);
            p[0] = make_uint4(f16pk(f0, f1), xs[0], xs[1], xs[2]);
            p[1] = make_uint4(xs[3], xs[4], 0u, 0u);
        }
        __syncthreads();

        // ============ phase 4: refine via mma (2 m-tiles per warp) ============
        {
            const char* rt = smem_raw + RT + (u32)lane * 272;
            const u32*    b1t = reinterpret_cast<const u32*>(rt);
            const float2* c1t = reinterpret_cast<const float2*>(rt + 64);
            const u32*    b2t = reinterpret_cast<const u32*>(rt + 128);
            const float2  c2  = *reinterpret_cast<const float2*>(rt + 160);
            float2* out2 = reinterpret_cast<float2*>(out);
            #pragma unroll 1
            for (int q = 0; q < 2; q++) {
                int mt = wid * 2 + q;
                u32 ax[4];
                ldm_x4(ax, sbase + RB + (u32)(mt * 16 + (lane & 15)) * 48
                           + ((lane >> 4) << 4));
                float d[8][4];
                #pragma unroll
                for (int nt = 0; nt < 8; nt++) {
                    float2 cc = c1t[nt];
                    mma_f16_c(d[nt][0], d[nt][1], d[nt][2], d[nt][3],
                              ax[0], ax[1], ax[2], ax[3],
                              b1t[2*nt], b1t[2*nt+1], cc.x, cc.y);
                }
                u32 a2[4][4];
                #pragma unroll
                for (int kt = 0; kt < 4; kt++) {
                    a2[kt][0] = relu_pk(d[2*kt][0],   d[2*kt][1]);
                    a2[kt][1] = relu_pk(d[2*kt][2],   d[2*kt][3]);
                    a2[kt][2] = relu_pk(d[2*kt+1][0], d[2*kt+1][1]);
                    a2[kt][3] = relu_pk(d[2*kt+1][2], d[2*kt+1][3]);
                }
                float y0, y1, y2, y3;
                mma_f16_c(y0, y1, y2, y3,
                          a2[0][0], a2[0][1], a2[0][2], a2[0][3],
                          b2t[0], b2t[1], c2.x, c2.y);
                #pragma unroll
                for (int kt = 1; kt < 4; kt++)
                    mma_f16_acc(y0, y1, y2, y3,
                                a2[kt][0], a2[kt][1], a2[kt][2], a2[kt][3],
                                b2t[2*kt], b2t[2*kt+1]);
                if (tig == 0) {
                    int rowA = tile * 256 + mt * 16 + grp;
                    out2[rowA]     = make_float2(tanh_acc(y0), tanh_acc(y1));
                    out2[rowA + 8] = make_float2(tanh_acc(y2), tanh_acc(y3));
                }
            }
        }
    }
}

extern "C" void kernel_launch(void* const* d_in, const int* in_sizes, int n_in,
                              void* d_out, int out_size)
{
    (void)in_sizes; (void)n_in; (void)out_size;
    const float* X   = (const float*)d_in[0];
    const float* W1  = (const float*)d_in[1];
    const float* b1  = (const float*)d_in[2];
    const float* W2  = (const float*)d_in[3];
    const float* b2  = (const float*)d_in[4];
    const float* W3  = (const float*)d_in[5];
    const float* b3  = (const float*)d_in[6];
    const float* G1  = (const float*)d_in[7];
    const float* gb1 = (const float*)d_in[8];
    const float* G2  = (const float*)d_in[9];
    const float* gb2 = (const float*)d_in[10];
    const float* R1  = (const float*)d_in[11];
    const float* rb1 = (const float*)d_in[12];
    const float* R2  = (const float*)d_in[13];
    const float* rb2 = (const float*)d_in[14];

    cudaFuncSetAttribute(moe_r11_kernel,
                         cudaFuncAttributeMaxDynamicSharedMemorySize, SMEM_TOTAL);

    moe_r11_kernel<<<GRID, 256, SMEM_TOTAL>>>(
        X, W1, b1, W2, b2, W3, b3, G1, gb1, G2, gb2, R1, rb1, R2, rb2,
        (float*)d_out);
}